// round 12
// baseline (speedup 1.0000x reference)
#include <cuda_runtime.h>
#include <cuda_bf16.h>
#include <cuda_fp16.h>
#include <cstdint>

#define NN 100000
#define EE 1600000
#define ETOT (EE + NN)
#define FIN 128
#define H1D 128
#define H2D 64
#define FC1D 128
#define NCLS 10
#define MM 20000
#define SLOPE 0.2f
#define NB1 ((NN + 1023) / 1024)

// ---------------- scratch (device globals; no allocations allowed) ----------
__device__ int g_maskbuf[MM];
__device__ int g_cnt[NN];                       // zero-init; re-zeroed by scatter
__device__ int g_rowptr[NN + 1];
__device__ int g_cursor[NN];
__device__ int g_col[ETOT];
__device__ int g_bsum[NB1];
__device__ __half g_hh[(size_t)NN * H1D];       // fp16 h (for gather)
__device__ float g_out1[(size_t)NN * H1D];
__device__ float g_out2[(size_t)NN * H2D];
__device__ float g_as[NN];
__device__ float g_ad[NN];

// ---------------- mma helpers (sm_80-portable HMMA path) ---------------------
__device__ __forceinline__ uint32_t smem_to_u32(const void* p) {
    uint32_t a;
    asm("{ .reg .u64 t; cvta.to.shared.u64 t, %1; cvt.u32.u64 %0, t; }" : "=r"(a) : "l"(p));
    return a;
}
__device__ __forceinline__ void ldsm_x4(uint32_t* r, uint32_t addr) {
    asm volatile("ldmatrix.sync.aligned.m8n8.x4.shared.b16 {%0,%1,%2,%3}, [%4];"
        : "=r"(r[0]), "=r"(r[1]), "=r"(r[2]), "=r"(r[3]) : "r"(addr));
}
__device__ __forceinline__ void ldsm_x4_t(uint32_t* r, uint32_t addr) {
    asm volatile("ldmatrix.sync.aligned.m8n8.x4.trans.shared.b16 {%0,%1,%2,%3}, [%4];"
        : "=r"(r[0]), "=r"(r[1]), "=r"(r[2]), "=r"(r[3]) : "r"(addr));
}
__device__ __forceinline__ void mma_bf16(float* c, const uint32_t* a, uint32_t b0, uint32_t b1) {
    asm volatile(
        "mma.sync.aligned.m16n8k16.row.col.f32.bf16.bf16.f32 "
        "{%0,%1,%2,%3}, {%4,%5,%6,%7}, {%8,%9}, {%0,%1,%2,%3};"
        : "+f"(c[0]), "+f"(c[1]), "+f"(c[2]), "+f"(c[3])
        : "r"(a[0]), "r"(a[1]), "r"(a[2]), "r"(a[3]), "r"(b0), "r"(b1));
}
__device__ __forceinline__ uint32_t pack2bf(float x, float y) {
    __nv_bfloat162 h = __floats2bfloat162_rn(x, y);
    return *reinterpret_cast<uint32_t*>(&h);
}
__device__ __forceinline__ bool edges_is64(const void* edges) {
    const int* q = (const int*)edges;
    return (q[1] | q[3] | q[5] | q[7] | q[9] | q[11] | q[13] | q[15]) == 0;
}

// ---------------- CSR build ---------------------------------------------------
__global__ void convert_hist_kernel(const void* edges, const void* mask) {
    int i = blockIdx.x * blockDim.x + threadIdx.x;
    bool is64 = edges_is64(edges);
    if (i < EE) {
        int d = is64 ? (int)((const long long*)edges)[EE + i]
                     : ((const int*)edges)[EE + i];
        atomicAdd(&g_cnt[d], 1);
    } else if (i < EE + MM) {
        int j = i - EE;
        g_maskbuf[j] = is64 ? (int)((const long long*)mask)[j]
                            : ((const int*)mask)[j];
    }
}

__global__ void scan1_kernel() {
    __shared__ int sh[1024];
    int t = threadIdx.x;
    int gid = blockIdx.x * 1024 + t;
    int v = (gid < NN) ? (g_cnt[gid] + 1) : 0;   // +1 = self loop
    sh[t] = v;
    __syncthreads();
    for (int off = 1; off < 1024; off <<= 1) {
        int tv = (t >= off) ? sh[t - off] : 0;
        __syncthreads();
        sh[t] += tv;
        __syncthreads();
    }
    if (gid < NN) g_rowptr[gid] = sh[t] - v;
    if (t == 1023) g_bsum[blockIdx.x] = sh[1023];
}

__global__ void scan3_kernel() {
    __shared__ int sh[256];
    int t = threadIdx.x;
    int blk = (blockIdx.x * 256) >> 10;
    sh[t] = (t < blk) ? g_bsum[t] : 0;
    __syncthreads();
    for (int off = 128; off; off >>= 1) {
        if (t < off) sh[t] += sh[t + off];
        __syncthreads();
    }
    int offset = sh[0];
    int gid = blockIdx.x * 256 + t;
    if (gid < NN) {
        int r = g_rowptr[gid] + offset;
        g_rowptr[gid] = r;
        g_cursor[gid] = r;
    }
    if (gid == 0) g_rowptr[NN] = ETOT;
}

__global__ void scatter_kernel(const void* edges) {
    int i = blockIdx.x * blockDim.x + threadIdx.x;
    if (i >= ETOT) return;
    if (i < NN) g_cnt[i] = 0;                    // cleanup for next replay
    int s, d;
    if (i < EE) {
        if (edges_is64(edges)) {
            const long long* e = (const long long*)edges;
            s = (int)e[i];
            d = (int)e[EE + i];
        } else {
            const int* e = (const int*)edges;
            s = e[i];
            d = e[EE + i];
        }
    } else {
        s = d = i - EE;
    }
    int pos = atomicAdd(&g_cursor[d], 1);
    g_col[pos] = s;
}

// ---------------- HMMA bf16-split GEMM + fused alpha, fp16-only output -------
// 256 threads / 8 warps (4 m-groups x 2 n-groups), warp tile 32 x (NOUT/2).
// MI=2 amortizes B ldsm across two m16 tiles: 12 ldsm per 48 mma.
// K=128 staged in two 64-wide chunks; 2 CTAs/SM.
template <int NOUT>
__global__ __launch_bounds__(256, 2)
void mma_gemm_kernel(const float* __restrict__ A, const float* __restrict__ W,
                     const float* __restrict__ a_src, const float* __restrict__ a_dst,
                     __half* __restrict__ Ch, int nrows) {
    extern __shared__ char smem[];
    constexpr int ROWB = NOUT * 2;               // bytes per B smem k-row
    constexpr int OFF_AH = 0;                    // 128 x 64 bf16 (128B rows)
    constexpr int OFF_AL = 128 * 128;
    constexpr int OFF_BH = 2 * 128 * 128;        // 64 k-rows x NOUT bf16
    constexpr int OFF_BL = OFF_BH + 64 * ROWB;
    constexpr int OFF_SA = OFF_BH + 2 * 64 * ROWB;
    constexpr int OFF_SAL = OFF_SA + 2 * NOUT * 4;
    constexpr int NP = NOUT / 32;                // ldsm_t groups per warp (4 / 2)
    constexpr int NT = 2 * NP;                   // n8-tiles per warp (8 / 4)

    const int tid = threadIdx.x;
    const int wid = tid >> 5, lane = tid & 31;
    const int row0 = blockIdx.x * 128;
    const uint32_t sbase = smem_to_u32(smem);
    float* sa = (float*)(smem + OFF_SA);
    float* sd = sa + NOUT;
    float* sal = (float*)(smem + OFF_SAL);

    if (tid < NOUT) {
        sa[tid] = a_src[tid];
        sd[tid] = a_dst[tid];
    }
    if (tid < 256) sal[tid] = 0.f;               // 128 rows x {s,d}

    // warp tiling: 4 m-groups of 32 rows x 2 n-groups of NOUT/2
    const int m0w = (wid >> 1) * 32;
    const int wn  = (wid & 1) * (NOUT / 2);

    float acc[2][NT][4];
#pragma unroll
    for (int mi = 0; mi < 2; mi++)
#pragma unroll
        for (int nt = 0; nt < NT; nt++)
#pragma unroll
            for (int q = 0; q < 4; q++) acc[mi][nt][q] = 0.f;

    const int a_row = lane & 15;
    const int a_cadd = lane >> 4;
    const int b_row = lane & 15;
    const int b_cadd = lane >> 4;

#pragma unroll
    for (int c = 0; c < 2; c++) {
        if (c) __syncthreads();                  // all warps done with chunk 0
        // ---- stage A chunk [128 x 64] fp32 -> bf16 hi/lo ----
#pragma unroll
        for (int it = 0; it < 8; it++) {
            int idx4 = tid + it * 256;
            int r = idx4 >> 4;
            int k4 = (idx4 & 15) * 4;
            int gr = row0 + r;
            float4 v = (gr < nrows) ? *(const float4*)&A[(size_t)gr * 128 + c * 64 + k4]
                                    : make_float4(0.f, 0.f, 0.f, 0.f);
            float hx = __bfloat162float(__float2bfloat16(v.x));
            float hy = __bfloat162float(__float2bfloat16(v.y));
            float hz = __bfloat162float(__float2bfloat16(v.z));
            float hw = __bfloat162float(__float2bfloat16(v.w));
            uint2 uh = make_uint2(pack2bf(v.x, v.y), pack2bf(v.z, v.w));
            uint2 ul = make_uint2(pack2bf(v.x - hx, v.y - hy), pack2bf(v.z - hz, v.w - hw));
            uint32_t off = (uint32_t)r * 128 + ((((k4 >> 3) ^ (r & 7)) << 4) + (k4 & 7) * 2);
            *(uint2*)(smem + OFF_AH + off) = uh;
            *(uint2*)(smem + OFF_AL + off) = ul;
        }
        // ---- stage B chunk [64 x NOUT] ----
        constexpr int QPR = NOUT / 4;
        constexpr int BITER = 64 * QPR / 256;
#pragma unroll
        for (int it = 0; it < BITER; it++) {
            int idx = tid + it * 256;
            int kk = idx / QPR;
            int n4 = (idx % QPR) * 4;
            float4 v = *(const float4*)&W[(size_t)(c * 64 + kk) * NOUT + n4];
            float hx = __bfloat162float(__float2bfloat16(v.x));
            float hy = __bfloat162float(__float2bfloat16(v.y));
            float hz = __bfloat162float(__float2bfloat16(v.z));
            float hw = __bfloat162float(__float2bfloat16(v.w));
            uint2 uh = make_uint2(pack2bf(v.x, v.y), pack2bf(v.z, v.w));
            uint2 ul = make_uint2(pack2bf(v.x - hx, v.y - hy), pack2bf(v.z - hz, v.w - hw));
            uint32_t off = (uint32_t)kk * ROWB + ((((n4 >> 3) ^ (kk & 7)) << 4) + (n4 & 7) * 2);
            *(uint2*)(smem + OFF_BH + off) = uh;
            *(uint2*)(smem + OFF_BL + off) = ul;
        }
        __syncthreads();

        // ---- 4 k-steps of 16 within this chunk ----
#pragma unroll
        for (int ks = 0; ks < 4; ks++) {
            uint32_t ah[2][4], al[2][4];
#pragma unroll
            for (int mi = 0; mi < 2; mi++) {
                int r = m0w + mi * 16 + a_row;
                int chunk = ks * 2 + a_cadd;
                uint32_t off = (uint32_t)r * 128 + (((chunk ^ (r & 7)) & 7) << 4);
                ldsm_x4(ah[mi], sbase + OFF_AH + off);
                ldsm_x4(al[mi], sbase + OFF_AL + off);
            }
#pragma unroll
            for (int p = 0; p < NP; p++) {
                int nbase = wn + p * 16;
                int r = ks * 16 + b_row;
                int chunkb = (nbase >> 3) + b_cadd;
                uint32_t off = (uint32_t)r * ROWB + (((chunkb ^ (r & 7)) & (ROWB / 16 - 1)) << 4);
                uint32_t bh[4], bl[4];
                ldsm_x4_t(bh, sbase + OFF_BH + off);
                ldsm_x4_t(bl, sbase + OFF_BL + off);
#pragma unroll
                for (int mi = 0; mi < 2; mi++) {
                    mma_bf16(acc[mi][2 * p],     ah[mi], bh[0], bh[1]);
                    mma_bf16(acc[mi][2 * p + 1], ah[mi], bh[2], bh[3]);
                    mma_bf16(acc[mi][2 * p],     ah[mi], bl[0], bl[1]);
                    mma_bf16(acc[mi][2 * p + 1], ah[mi], bl[2], bl[3]);
                    mma_bf16(acc[mi][2 * p],     al[mi], bh[0], bh[1]);
                    mma_bf16(acc[mi][2 * p + 1], al[mi], bh[2], bh[3]);
                }
            }
        }
    }

    // ---- epilogue: fp16 store + fused alpha reduction ----
    const int group = lane >> 2;
    const int tc = (lane & 3) * 2;
#pragma unroll
    for (int mi = 0; mi < 2; mi++) {
        int r0 = row0 + m0w + mi * 16 + group;
        int r1 = r0 + 8;
        float s0 = 0.f, d0 = 0.f, s1 = 0.f, d1 = 0.f;
#pragma unroll
        for (int nt = 0; nt < NT; nt++) {
            int col = wn + nt * 8 + tc;
            float va0 = sa[col], va1 = sa[col + 1];
            float vd0 = sd[col], vd1 = sd[col + 1];
            s0 += acc[mi][nt][0] * va0 + acc[mi][nt][1] * va1;
            d0 += acc[mi][nt][0] * vd0 + acc[mi][nt][1] * vd1;
            s1 += acc[mi][nt][2] * va0 + acc[mi][nt][3] * va1;
            d1 += acc[mi][nt][2] * vd0 + acc[mi][nt][3] * vd1;
            if (r0 < nrows)
                *(__half2*)&Ch[(size_t)r0 * NOUT + col] = __floats2half2_rn(acc[mi][nt][0], acc[mi][nt][1]);
            if (r1 < nrows)
                *(__half2*)&Ch[(size_t)r1 * NOUT + col] = __floats2half2_rn(acc[mi][nt][2], acc[mi][nt][3]);
        }
#pragma unroll
        for (int m = 1; m <= 2; m <<= 1) {
            s0 += __shfl_xor_sync(0xffffffffu, s0, m);
            d0 += __shfl_xor_sync(0xffffffffu, d0, m);
            s1 += __shfl_xor_sync(0xffffffffu, s1, m);
            d1 += __shfl_xor_sync(0xffffffffu, d1, m);
        }
        if ((lane & 3) == 0) {
            int rl = m0w + mi * 16 + group;
            atomicAdd(&sal[rl * 2], s0);
            atomicAdd(&sal[rl * 2 + 1], d0);
            atomicAdd(&sal[(rl + 8) * 2], s1);
            atomicAdd(&sal[(rl + 8) * 2 + 1], d1);
        }
    }
    __syncthreads();
    if (tid < 128) {
        int row = row0 + tid;
        if (row < nrows) {
            g_as[row] = sal[tid * 2];
            g_ad[row] = sal[tid * 2 + 1];
        }
    }
}

// ---------------- fused softmax + gather: warp per node, fp16 h, 4-unroll ----
template <int F>
__global__ void agg_kernel(const __half* __restrict__ hh, const float* __restrict__ bias,
                           float* __restrict__ out) {
    constexpr int V = F / 32;
    int node = (blockIdx.x * blockDim.x + threadIdx.x) >> 5;
    int lane = threadIdx.x & 31;
    if (node >= NN) return;
    int idx = g_rowptr[node];
    const int end = g_rowptr[node + 1];
    const float adv = g_ad[node];
    float mm = g_as[node] + adv;
    const float m = (mm > 0.f) ? mm : SLOPE * mm;
    float Z = 0.f;
    float acc[V];
#pragma unroll
    for (int j = 0; j < V; j++) acc[j] = 0.f;

    for (; idx + 4 <= end; idx += 4) {
        int s0 = g_col[idx];
        int s1 = g_col[idx + 1];
        int s2 = g_col[idx + 2];
        int s3 = g_col[idx + 3];
        float e0 = g_as[s0] + adv;
        float e1 = g_as[s1] + adv;
        float e2 = g_as[s2] + adv;
        float e3 = g_as[s3] + adv;
        e0 = (e0 > 0.f) ? e0 : SLOPE * e0;
        e1 = (e1 > 0.f) ? e1 : SLOPE * e1;
        e2 = (e2 > 0.f) ? e2 : SLOPE * e2;
        e3 = (e3 > 0.f) ? e3 : SLOPE * e3;
        float w0 = __expf(e0 - m);
        float w1 = __expf(e1 - m);
        float w2 = __expf(e2 - m);
        float w3 = __expf(e3 - m);
        Z += (w0 + w1) + (w2 + w3);
        if (V == 4) {
            uint2 u0 = *(const uint2*)&hh[(size_t)s0 * F + lane * 4];
            uint2 u1 = *(const uint2*)&hh[(size_t)s1 * F + lane * 4];
            uint2 u2 = *(const uint2*)&hh[(size_t)s2 * F + lane * 4];
            uint2 u3 = *(const uint2*)&hh[(size_t)s3 * F + lane * 4];
            float2 a0 = __half22float2(*(const __half2*)&u0.x);
            float2 b0 = __half22float2(*(const __half2*)&u0.y);
            float2 a1 = __half22float2(*(const __half2*)&u1.x);
            float2 b1 = __half22float2(*(const __half2*)&u1.y);
            float2 a2 = __half22float2(*(const __half2*)&u2.x);
            float2 b2 = __half22float2(*(const __half2*)&u2.y);
            float2 a3 = __half22float2(*(const __half2*)&u3.x);
            float2 b3 = __half22float2(*(const __half2*)&u3.y);
            acc[0] += (w0 * a0.x + w1 * a1.x) + (w2 * a2.x + w3 * a3.x);
            acc[1] += (w0 * a0.y + w1 * a1.y) + (w2 * a2.y + w3 * a3.y);
            acc[2] += (w0 * b0.x + w1 * b1.x) + (w2 * b2.x + w3 * b3.x);
            acc[3] += (w0 * b0.y + w1 * b1.y) + (w2 * b2.y + w3 * b3.y);
        } else {
            float2 a0 = __half22float2(*(const __half2*)&hh[(size_t)s0 * F + lane * 2]);
            float2 a1 = __half22float2(*(const __half2*)&hh[(size_t)s1 * F + lane * 2]);
            float2 a2 = __half22float2(*(const __half2*)&hh[(size_t)s2 * F + lane * 2]);
            float2 a3 = __half22float2(*(const __half2*)&hh[(size_t)s3 * F + lane * 2]);
            acc[0] += (w0 * a0.x + w1 * a1.x) + (w2 * a2.x + w3 * a3.x);
            acc[1] += (w0 * a0.y + w1 * a1.y) + (w2 * a2.y + w3 * a3.y);
        }
    }
    for (; idx < end; idx++) {
        int s0 = g_col[idx];
        float e0 = g_as[s0] + adv;
        e0 = (e0 > 0.f) ? e0 : SLOPE * e0;
        float w0 = __expf(e0 - m);
        Z += w0;
        if (V == 4) {
            uint2 u0 = *(const uint2*)&hh[(size_t)s0 * F + lane * 4];
            float2 a0 = __half22float2(*(const __half2*)&u0.x);
            float2 b0 = __half22float2(*(const __half2*)&u0.y);
            acc[0] += w0 * a0.x; acc[1] += w0 * a0.y;
            acc[2] += w0 * b0.x; acc[3] += w0 * b0.y;
        } else {
            float2 a0 = __half22float2(*(const __half2*)&hh[(size_t)s0 * F + lane * 2]);
            acc[0] += w0 * a0.x; acc[1] += w0 * a0.y;
        }
    }

    const float iz = 1.f / Z;
    if (V == 4) {
        float4 b4 = *(const float4*)&bias[lane * 4];
        float4 o;
        o.x = fmaxf(acc[0] * iz + b4.x, 0.f);
        o.y = fmaxf(acc[1] * iz + b4.y, 0.f);
        o.z = fmaxf(acc[2] * iz + b4.z, 0.f);
        o.w = fmaxf(acc[3] * iz + b4.w, 0.f);
        *(float4*)&out[(size_t)node * F + lane * 4] = o;
    } else {
        float2 b2 = *(const float2*)&bias[lane * 2];
        float2 o;
        o.x = fmaxf(acc[0] * iz + b2.x, 0.f);
        o.y = fmaxf(acc[1] * iz + b2.y, 0.f);
        *(float2*)&out[(size_t)node * F + lane * 2] = o;
    }
}

// ---------------- FC head: 32 mask-nodes per block, weights staged in smem ---
#define FCNPB 32
__global__ __launch_bounds__(256)
void fc_kernel(const float* __restrict__ feat,
               const float* __restrict__ w1, const float* __restrict__ b1,
               const float* __restrict__ w2, const float* __restrict__ b2,
               float* __restrict__ out) {
    extern __shared__ float sm[];
    float* sw1 = sm;
    float* sw2 = sw1 + 64 * 128;
    float* sf  = sw2 + 128 * 12;
    float* sz  = sf + FCNPB * 64;

    const int tid = threadIdx.x;
    const int mi0 = blockIdx.x * FCNPB;

#pragma unroll
    for (int it = 0; it < 8; it++) {
        int i4 = tid + it * 256;
        *(float4*)&sw1[i4 * 4] = *(const float4*)&w1[i4 * 4];
    }
    for (int i = tid; i < 128 * NCLS; i += 256)
        sw2[(i / NCLS) * 12 + (i % NCLS)] = w2[i];
#pragma unroll
    for (int it = 0; it < 2; it++) {
        int i4 = tid + it * 256;
        int n = i4 >> 4;
        int c4 = (i4 & 15) * 4;
        int node = g_maskbuf[mi0 + n];
        *(float4*)&sf[n * 64 + c4] = *(const float4*)&feat[(size_t)node * H2D + c4];
    }
    __syncthreads();

#pragma unroll
    for (int it = 0; it < 16; it++) {
        int oi = tid + it * 256;
        int n = oi >> 7;
        int t = oi & 127;
        float acc = b1[t];
#pragma unroll
        for (int k = 0; k < 64; k++)
            acc += sf[n * 64 + k] * sw1[k * 128 + t];
        sz[n * 128 + t] = fmaxf(acc, 0.f);
    }
    __syncthreads();

    for (int oi = tid; oi < FCNPB * NCLS; oi += 256) {
        int n = oi / NCLS;
        int c = oi % NCLS;
        float acc = b2[c];
#pragma unroll
        for (int j = 0; j < 128; j++)
            acc += sz[n * 128 + j] * sw2[j * 12 + c];
        out[(size_t)(mi0 + n) * NCLS + c] = acc;
    }
}

// ---------------- launch -----------------------------------------------------
extern "C" void kernel_launch(void* const* d_in, const int* in_sizes, int n_in,
                              void* d_out, int out_size) {
    const float* x      = (const float*)d_in[0];
    const void*  edges  = d_in[1];
    const void*  mask   = d_in[2];
    const float* W1     = (const float*)d_in[3];
    const float* a_src1 = (const float*)d_in[4];
    const float* a_dst1 = (const float*)d_in[5];
    const float* b1     = (const float*)d_in[6];
    const float* W2     = (const float*)d_in[7];
    const float* a_src2 = (const float*)d_in[8];
    const float* a_dst2 = (const float*)d_in[9];
    const float* b2     = (const float*)d_in[10];
    const float* fc1_w  = (const float*)d_in[11];
    const float* fc1_b  = (const float*)d_in[12];
    const float* fc2_w  = (const float*)d_in[13];
    const float* fc2_b  = (const float*)d_in[14];
    float* out = (float*)d_out;

    __half* g_hh_p;   cudaGetSymbolAddress((void**)&g_hh_p, g_hh);
    float* g_out1_p;  cudaGetSymbolAddress((void**)&g_out1_p, g_out1);
    float* g_out2_p;  cudaGetSymbolAddress((void**)&g_out2_p, g_out2);

    // smem: A 2*128*128 + B 2*64*ROWB + sa/sd + sal
    const int smem128 = 2 * 128 * 128 + 2 * 64 * 256 + 2 * 128 * 4 + 256 * 4;  // 67584
    const int smem64  = 2 * 128 * 128 + 2 * 64 * 128 + 2 * 64 * 4 + 256 * 4;   // 50688
    const int smemFc  = (64 * 128 + 128 * 12 + FCNPB * 64 + FCNPB * 128) * 4;  // 63488
    cudaFuncSetAttribute(mma_gemm_kernel<128>, cudaFuncAttributeMaxDynamicSharedMemorySize, smem128);
    cudaFuncSetAttribute(mma_gemm_kernel<64>,  cudaFuncAttributeMaxDynamicSharedMemorySize, smem64);
    cudaFuncSetAttribute(fc_kernel, cudaFuncAttributeMaxDynamicSharedMemorySize, smemFc);

    const int warpBlocks = (NN * 32 + 255) / 256;
    const int gemmBlocks = (NN + 127) / 128;

    convert_hist_kernel<<<(EE + MM + 255) / 256, 256>>>(edges, mask);
    scan1_kernel<<<NB1, 1024>>>();
    scan3_kernel<<<(NN + 255) / 256, 256>>>();
    mma_gemm_kernel<128><<<gemmBlocks, 256, smem128>>>(x, W1, a_src1, a_dst1, g_hh_p, NN);
    scatter_kernel<<<(ETOT + 255) / 256, 256>>>(edges);
    agg_kernel<H1D><<<warpBlocks, 256>>>(g_hh_p, b1, g_out1_p);

    mma_gemm_kernel<64><<<gemmBlocks, 256, smem64>>>(g_out1_p, W2, a_src2, a_dst2, g_hh_p, NN);
    agg_kernel<H2D><<<warpBlocks, 256>>>(g_hh_p, b2, g_out2_p);

    fc_kernel<<<MM / FCNPB, 256, smemFc>>>(g_out2_p, fc1_w, fc1_b, fc2_w, fc2_b, out);
}

// round 13
// speedup vs baseline: 1.0120x; 1.0120x over previous
#include <cuda_runtime.h>
#include <cuda_bf16.h>
#include <cuda_fp16.h>
#include <cstdint>

#define NN 100000
#define EE 1600000
#define ETOT (EE + NN)
#define FIN 128
#define H1D 128
#define H2D 64
#define FC1D 128
#define NCLS 10
#define MM 20000
#define SLOPE 0.2f
#define NB1 ((NN + 1023) / 1024)

// ---------------- scratch (device globals; no allocations allowed) ----------
__device__ int g_maskbuf[MM];
__device__ int g_cnt[NN];                       // zero-init; re-zeroed by scatter
__device__ int g_rowptr[NN + 1];
__device__ int g_cursor[NN];
__device__ int g_col[ETOT];
__device__ int g_bsum[NB1];
__device__ __half g_hh[(size_t)NN * H1D];       // fp16 h (for gather)
__device__ float g_out1[(size_t)NN * H1D];
__device__ float g_out2[(size_t)NN * H2D];
__device__ float g_as[NN];
__device__ float g_ad[NN];

// ---------------- mma helpers (sm_80-portable HMMA path) ---------------------
__device__ __forceinline__ uint32_t smem_to_u32(const void* p) {
    uint32_t a;
    asm("{ .reg .u64 t; cvta.to.shared.u64 t, %1; cvt.u32.u64 %0, t; }" : "=r"(a) : "l"(p));
    return a;
}
__device__ __forceinline__ void ldsm_x4(uint32_t* r, uint32_t addr) {
    asm volatile("ldmatrix.sync.aligned.m8n8.x4.shared.b16 {%0,%1,%2,%3}, [%4];"
        : "=r"(r[0]), "=r"(r[1]), "=r"(r[2]), "=r"(r[3]) : "r"(addr));
}
__device__ __forceinline__ void ldsm_x4_t(uint32_t* r, uint32_t addr) {
    asm volatile("ldmatrix.sync.aligned.m8n8.x4.trans.shared.b16 {%0,%1,%2,%3}, [%4];"
        : "=r"(r[0]), "=r"(r[1]), "=r"(r[2]), "=r"(r[3]) : "r"(addr));
}
__device__ __forceinline__ void mma_bf16(float* c, const uint32_t* a, uint32_t b0, uint32_t b1) {
    asm volatile(
        "mma.sync.aligned.m16n8k16.row.col.f32.bf16.bf16.f32 "
        "{%0,%1,%2,%3}, {%4,%5,%6,%7}, {%8,%9}, {%0,%1,%2,%3};"
        : "+f"(c[0]), "+f"(c[1]), "+f"(c[2]), "+f"(c[3])
        : "r"(a[0]), "r"(a[1]), "r"(a[2]), "r"(a[3]), "r"(b0), "r"(b1));
}
__device__ __forceinline__ uint32_t pack2bf(float x, float y) {
    __nv_bfloat162 h = __floats2bfloat162_rn(x, y);
    return *reinterpret_cast<uint32_t*>(&h);
}
__device__ __forceinline__ bool edges_is64(const void* edges) {
    const int* q = (const int*)edges;
    return (q[1] | q[3] | q[5] | q[7] | q[9] | q[11] | q[13] | q[15]) == 0;
}

// ---------------- CSR build ---------------------------------------------------
__global__ void convert_hist_kernel(const void* edges, const void* mask) {
    int i = blockIdx.x * blockDim.x + threadIdx.x;
    bool is64 = edges_is64(edges);
    if (i < EE) {
        int d = is64 ? (int)((const long long*)edges)[EE + i]
                     : ((const int*)edges)[EE + i];
        atomicAdd(&g_cnt[d], 1);
    } else if (i < EE + MM) {
        int j = i - EE;
        g_maskbuf[j] = is64 ? (int)((const long long*)mask)[j]
                            : ((const int*)mask)[j];
    }
}

__global__ void scan1_kernel() {
    __shared__ int sh[1024];
    int t = threadIdx.x;
    int gid = blockIdx.x * 1024 + t;
    int v = (gid < NN) ? (g_cnt[gid] + 1) : 0;   // +1 = self loop
    sh[t] = v;
    __syncthreads();
    for (int off = 1; off < 1024; off <<= 1) {
        int tv = (t >= off) ? sh[t - off] : 0;
        __syncthreads();
        sh[t] += tv;
        __syncthreads();
    }
    if (gid < NN) g_rowptr[gid] = sh[t] - v;
    if (t == 1023) g_bsum[blockIdx.x] = sh[1023];
}

__global__ void scan3_kernel() {
    __shared__ int sh[256];
    int t = threadIdx.x;
    int blk = (blockIdx.x * 256) >> 10;
    sh[t] = (t < blk) ? g_bsum[t] : 0;
    __syncthreads();
    for (int off = 128; off; off >>= 1) {
        if (t < off) sh[t] += sh[t + off];
        __syncthreads();
    }
    int offset = sh[0];
    int gid = blockIdx.x * 256 + t;
    if (gid < NN) {
        int r = g_rowptr[gid] + offset;
        g_rowptr[gid] = r;
        g_cursor[gid] = r;
    }
    if (gid == 0) g_rowptr[NN] = ETOT;
}

__global__ void scatter_kernel(const void* edges) {
    int i = blockIdx.x * blockDim.x + threadIdx.x;
    if (i >= ETOT) return;
    if (i < NN) g_cnt[i] = 0;                    // cleanup for next replay
    int s, d;
    if (i < EE) {
        if (edges_is64(edges)) {
            const long long* e = (const long long*)edges;
            s = (int)e[i];
            d = (int)e[EE + i];
        } else {
            const int* e = (const int*)edges;
            s = e[i];
            d = e[EE + i];
        }
    } else {
        s = d = i - EE;
    }
    int pos = atomicAdd(&g_cursor[d], 1);
    g_col[pos] = s;
}

// ---------------- HMMA bf16-split GEMM + fused alpha, fp16-only output -------
// R11 config: 256 threads / 8 warps, 2 CTAs per SM. CTA tile AROWS x NOUT,
// warp tile 16x64. K=128 staged in two 64-wide chunks.
template <int NOUT>
__global__ __launch_bounds__(256, 2)
void mma_gemm_kernel(const float* __restrict__ A, const float* __restrict__ W,
                     const float* __restrict__ a_src, const float* __restrict__ a_dst,
                     __half* __restrict__ Ch, int nrows) {
    extern __shared__ char smem[];
    constexpr int AROWS = (NOUT == 128) ? 64 : 128;
    constexpr int ROWB = NOUT * 2;               // bytes per B smem k-row
    constexpr int OFF_AH = 0;                    // AROWS x 64 bf16 (128B rows)
    constexpr int OFF_AL = AROWS * 128;
    constexpr int OFF_BH = 2 * AROWS * 128;      // 64 k-rows x NOUT bf16
    constexpr int OFF_BL = OFF_BH + 64 * ROWB;
    constexpr int OFF_SA = OFF_BH + 2 * 64 * ROWB;
    constexpr int OFF_SAL = OFF_SA + 2 * NOUT * 4;

    const int tid = threadIdx.x;
    const int wid = tid >> 5, lane = tid & 31;
    const int row0 = blockIdx.x * AROWS;
    const uint32_t sbase = smem_to_u32(smem);
    float* sa = (float*)(smem + OFF_SA);
    float* sd = sa + NOUT;
    float* sal = (float*)(smem + OFF_SAL);

    if (tid < NOUT) {
        sa[tid] = a_src[tid];
        sd[tid] = a_dst[tid];
    }
    if (tid < AROWS * 2) sal[tid] = 0.f;

    // warp tiling: 16x64 warp tiles
    const int m0w = (NOUT == 128) ? (wid >> 1) * 16 : wid * 16;
    const int wn  = (NOUT == 128) ? (wid & 1) * 64 : 0;

    float acc[8][4];
#pragma unroll
    for (int nt = 0; nt < 8; nt++)
#pragma unroll
        for (int q = 0; q < 4; q++) acc[nt][q] = 0.f;

    const int a_row = lane & 15;
    const int a_cadd = lane >> 4;
    const int b_row = lane & 15;
    const int b_cadd = lane >> 4;

#pragma unroll
    for (int c = 0; c < 2; c++) {
        if (c) __syncthreads();                  // all warps done with chunk 0
        // ---- stage A chunk [AROWS x 64] fp32 -> bf16 hi/lo ----
        constexpr int AITER = AROWS * 16 / 256;
#pragma unroll
        for (int it = 0; it < AITER; it++) {
            int idx4 = tid + it * 256;
            int r = idx4 >> 4;
            int k4 = (idx4 & 15) * 4;
            int gr = row0 + r;
            float4 v = (gr < nrows) ? *(const float4*)&A[(size_t)gr * 128 + c * 64 + k4]
                                    : make_float4(0.f, 0.f, 0.f, 0.f);
            float hx = __bfloat162float(__float2bfloat16(v.x));
            float hy = __bfloat162float(__float2bfloat16(v.y));
            float hz = __bfloat162float(__float2bfloat16(v.z));
            float hw = __bfloat162float(__float2bfloat16(v.w));
            uint2 uh = make_uint2(pack2bf(v.x, v.y), pack2bf(v.z, v.w));
            uint2 ul = make_uint2(pack2bf(v.x - hx, v.y - hy), pack2bf(v.z - hz, v.w - hw));
            uint32_t off = (uint32_t)r * 128 + ((((k4 >> 3) ^ (r & 7)) << 4) + (k4 & 7) * 2);
            *(uint2*)(smem + OFF_AH + off) = uh;
            *(uint2*)(smem + OFF_AL + off) = ul;
        }
        // ---- stage B chunk [64 x NOUT] ----
        constexpr int QPR = NOUT / 4;
        constexpr int BITER = 64 * QPR / 256;
#pragma unroll
        for (int it = 0; it < BITER; it++) {
            int idx = tid + it * 256;
            int kk = idx / QPR;
            int n4 = (idx % QPR) * 4;
            float4 v = *(const float4*)&W[(size_t)(c * 64 + kk) * NOUT + n4];
            float hx = __bfloat162float(__float2bfloat16(v.x));
            float hy = __bfloat162float(__float2bfloat16(v.y));
            float hz = __bfloat162float(__float2bfloat16(v.z));
            float hw = __bfloat162float(__float2bfloat16(v.w));
            uint2 uh = make_uint2(pack2bf(v.x, v.y), pack2bf(v.z, v.w));
            uint2 ul = make_uint2(pack2bf(v.x - hx, v.y - hy), pack2bf(v.z - hz, v.w - hw));
            uint32_t off = (uint32_t)kk * ROWB + ((((n4 >> 3) ^ (kk & 7)) << 4) + (n4 & 7) * 2);
            *(uint2*)(smem + OFF_BH + off) = uh;
            *(uint2*)(smem + OFF_BL + off) = ul;
        }
        __syncthreads();

        // ---- 4 k-steps of 16 within this chunk ----
#pragma unroll
        for (int ks = 0; ks < 4; ks++) {
            uint32_t ah[4], al[4];
            {
                int r = m0w + a_row;
                int chunk = ks * 2 + a_cadd;
                uint32_t off = (uint32_t)r * 128 + (((chunk ^ (r & 7)) & 7) << 4);
                ldsm_x4(ah, sbase + OFF_AH + off);
                ldsm_x4(al, sbase + OFF_AL + off);
            }
#pragma unroll
            for (int p = 0; p < 4; p++) {
                int nbase = wn + p * 16;
                int r = ks * 16 + b_row;
                int chunkb = (nbase >> 3) + b_cadd;
                uint32_t off = (uint32_t)r * ROWB + (((chunkb ^ (r & 7)) & (ROWB / 16 - 1)) << 4);
                uint32_t bh[4], bl[4];
                ldsm_x4_t(bh, sbase + OFF_BH + off);
                ldsm_x4_t(bl, sbase + OFF_BL + off);
                mma_bf16(acc[2 * p],     ah, bh[0], bh[1]);
                mma_bf16(acc[2 * p + 1], ah, bh[2], bh[3]);
                mma_bf16(acc[2 * p],     ah, bl[0], bl[1]);
                mma_bf16(acc[2 * p + 1], ah, bl[2], bl[3]);
                mma_bf16(acc[2 * p],     al, bh[0], bh[1]);
                mma_bf16(acc[2 * p + 1], al, bh[2], bh[3]);
            }
        }
    }

    // ---- epilogue: fp16 store + fused alpha reduction ----
    const int group = lane >> 2;
    const int tc = (lane & 3) * 2;
    {
        int r0 = row0 + m0w + group;
        int r1 = r0 + 8;
        float s0 = 0.f, d0 = 0.f, s1 = 0.f, d1 = 0.f;
#pragma unroll
        for (int nt = 0; nt < 8; nt++) {
            int col = wn + nt * 8 + tc;
            float va0 = sa[col], va1 = sa[col + 1];
            float vd0 = sd[col], vd1 = sd[col + 1];
            s0 += acc[nt][0] * va0 + acc[nt][1] * va1;
            d0 += acc[nt][0] * vd0 + acc[nt][1] * vd1;
            s1 += acc[nt][2] * va0 + acc[nt][3] * va1;
            d1 += acc[nt][2] * vd0 + acc[nt][3] * vd1;
            if (r0 < nrows)
                *(__half2*)&Ch[(size_t)r0 * NOUT + col] = __floats2half2_rn(acc[nt][0], acc[nt][1]);
            if (r1 < nrows)
                *(__half2*)&Ch[(size_t)r1 * NOUT + col] = __floats2half2_rn(acc[nt][2], acc[nt][3]);
        }
#pragma unroll
        for (int m = 1; m <= 2; m <<= 1) {
            s0 += __shfl_xor_sync(0xffffffffu, s0, m);
            d0 += __shfl_xor_sync(0xffffffffu, d0, m);
            s1 += __shfl_xor_sync(0xffffffffu, s1, m);
            d1 += __shfl_xor_sync(0xffffffffu, d1, m);
        }
        if ((lane & 3) == 0) {
            int rl = m0w + group;
            atomicAdd(&sal[rl * 2], s0);
            atomicAdd(&sal[rl * 2 + 1], d0);
            atomicAdd(&sal[(rl + 8) * 2], s1);
            atomicAdd(&sal[(rl + 8) * 2 + 1], d1);
        }
    }
    __syncthreads();
    if (tid < AROWS) {
        int row = row0 + tid;
        if (row < nrows) {
            g_as[row] = sal[tid * 2];
            g_ad[row] = sal[tid * 2 + 1];
        }
    }
}

// ---------------- fused softmax + gather: warp per node, fp16 h, 4-unroll ----
template <int F>
__global__ void agg_kernel(const __half* __restrict__ hh, const float* __restrict__ bias,
                           float* __restrict__ out) {
    constexpr int V = F / 32;
    int node = (blockIdx.x * blockDim.x + threadIdx.x) >> 5;
    int lane = threadIdx.x & 31;
    if (node >= NN) return;
    int idx = g_rowptr[node];
    const int end = g_rowptr[node + 1];
    const float adv = g_ad[node];
    float mm = g_as[node] + adv;
    const float m = (mm > 0.f) ? mm : SLOPE * mm;
    float Z = 0.f;
    float acc[V];
#pragma unroll
    for (int j = 0; j < V; j++) acc[j] = 0.f;

    for (; idx + 4 <= end; idx += 4) {
        int s0 = g_col[idx];
        int s1 = g_col[idx + 1];
        int s2 = g_col[idx + 2];
        int s3 = g_col[idx + 3];
        float e0 = g_as[s0] + adv;
        float e1 = g_as[s1] + adv;
        float e2 = g_as[s2] + adv;
        float e3 = g_as[s3] + adv;
        e0 = (e0 > 0.f) ? e0 : SLOPE * e0;
        e1 = (e1 > 0.f) ? e1 : SLOPE * e1;
        e2 = (e2 > 0.f) ? e2 : SLOPE * e2;
        e3 = (e3 > 0.f) ? e3 : SLOPE * e3;
        float w0 = __expf(e0 - m);
        float w1 = __expf(e1 - m);
        float w2 = __expf(e2 - m);
        float w3 = __expf(e3 - m);
        Z += (w0 + w1) + (w2 + w3);
        if (V == 4) {
            uint2 u0 = *(const uint2*)&hh[(size_t)s0 * F + lane * 4];
            uint2 u1 = *(const uint2*)&hh[(size_t)s1 * F + lane * 4];
            uint2 u2 = *(const uint2*)&hh[(size_t)s2 * F + lane * 4];
            uint2 u3 = *(const uint2*)&hh[(size_t)s3 * F + lane * 4];
            float2 a0 = __half22float2(*(const __half2*)&u0.x);
            float2 b0 = __half22float2(*(const __half2*)&u0.y);
            float2 a1 = __half22float2(*(const __half2*)&u1.x);
            float2 b1 = __half22float2(*(const __half2*)&u1.y);
            float2 a2 = __half22float2(*(const __half2*)&u2.x);
            float2 b2 = __half22float2(*(const __half2*)&u2.y);
            float2 a3 = __half22float2(*(const __half2*)&u3.x);
            float2 b3 = __half22float2(*(const __half2*)&u3.y);
            acc[0] += (w0 * a0.x + w1 * a1.x) + (w2 * a2.x + w3 * a3.x);
            acc[1] += (w0 * a0.y + w1 * a1.y) + (w2 * a2.y + w3 * a3.y);
            acc[2] += (w0 * b0.x + w1 * b1.x) + (w2 * b2.x + w3 * b3.x);
            acc[3] += (w0 * b0.y + w1 * b1.y) + (w2 * b2.y + w3 * b3.y);
        } else {
            float2 a0 = __half22float2(*(const __half2*)&hh[(size_t)s0 * F + lane * 2]);
            float2 a1 = __half22float2(*(const __half2*)&hh[(size_t)s1 * F + lane * 2]);
            float2 a2 = __half22float2(*(const __half2*)&hh[(size_t)s2 * F + lane * 2]);
            float2 a3 = __half22float2(*(const __half2*)&hh[(size_t)s3 * F + lane * 2]);
            acc[0] += (w0 * a0.x + w1 * a1.x) + (w2 * a2.x + w3 * a3.x);
            acc[1] += (w0 * a0.y + w1 * a1.y) + (w2 * a2.y + w3 * a3.y);
        }
    }
    for (; idx < end; idx++) {
        int s0 = g_col[idx];
        float e0 = g_as[s0] + adv;
        e0 = (e0 > 0.f) ? e0 : SLOPE * e0;
        float w0 = __expf(e0 - m);
        Z += w0;
        if (V == 4) {
            uint2 u0 = *(const uint2*)&hh[(size_t)s0 * F + lane * 4];
            float2 a0 = __half22float2(*(const __half2*)&u0.x);
            float2 b0 = __half22float2(*(const __half2*)&u0.y);
            acc[0] += w0 * a0.x; acc[1] += w0 * a0.y;
            acc[2] += w0 * b0.x; acc[3] += w0 * b0.y;
        } else {
            float2 a0 = __half22float2(*(const __half2*)&hh[(size_t)s0 * F + lane * 2]);
            acc[0] += w0 * a0.x; acc[1] += w0 * a0.y;
        }
    }

    const float iz = 1.f / Z;
    if (V == 4) {
        float4 b4 = *(const float4*)&bias[lane * 4];
        float4 o;
        o.x = fmaxf(acc[0] * iz + b4.x, 0.f);
        o.y = fmaxf(acc[1] * iz + b4.y, 0.f);
        o.z = fmaxf(acc[2] * iz + b4.z, 0.f);
        o.w = fmaxf(acc[3] * iz + b4.w, 0.f);
        *(float4*)&out[(size_t)node * F + lane * 4] = o;
    } else {
        float2 b2 = *(const float2*)&bias[lane * 2];
        float2 o;
        o.x = fmaxf(acc[0] * iz + b2.x, 0.f);
        o.y = fmaxf(acc[1] * iz + b2.y, 0.f);
        *(float2*)&out[(size_t)node * F + lane * 2] = o;
    }
}

// ---------------- FC head: 32 mask-nodes per block, weights staged in smem ---
#define FCNPB 32
__global__ __launch_bounds__(256)
void fc_kernel(const float* __restrict__ feat,
               const float* __restrict__ w1, const float* __restrict__ b1,
               const float* __restrict__ w2, const float* __restrict__ b2,
               float* __restrict__ out) {
    extern __shared__ float sm[];
    float* sw1 = sm;
    float* sw2 = sw1 + 64 * 128;
    float* sf  = sw2 + 128 * 12;
    float* sz  = sf + FCNPB * 64;

    const int tid = threadIdx.x;
    const int mi0 = blockIdx.x * FCNPB;

#pragma unroll
    for (int it = 0; it < 8; it++) {
        int i4 = tid + it * 256;
        *(float4*)&sw1[i4 * 4] = *(const float4*)&w1[i4 * 4];
    }
    for (int i = tid; i < 128 * NCLS; i += 256)
        sw2[(i / NCLS) * 12 + (i % NCLS)] = w2[i];
#pragma unroll
    for (int it = 0; it < 2; it++) {
        int i4 = tid + it * 256;
        int n = i4 >> 4;
        int c4 = (i4 & 15) * 4;
        int node = g_maskbuf[mi0 + n];
        *(float4*)&sf[n * 64 + c4] = *(const float4*)&feat[(size_t)node * H2D + c4];
    }
    __syncthreads();

#pragma unroll
    for (int it = 0; it < 16; it++) {
        int oi = tid + it * 256;
        int n = oi >> 7;
        int t = oi & 127;
        float acc = b1[t];
#pragma unroll
        for (int k = 0; k < 64; k++)
            acc += sf[n * 64 + k] * sw1[k * 128 + t];
        sz[n * 128 + t] = fmaxf(acc, 0.f);
    }
    __syncthreads();

    for (int oi = tid; oi < FCNPB * NCLS; oi += 256) {
        int n = oi / NCLS;
        int c = oi % NCLS;
        float acc = b2[c];
#pragma unroll
        for (int j = 0; j < 128; j++)
            acc += sz[n * 128 + j] * sw2[j * 12 + c];
        out[(size_t)(mi0 + n) * NCLS + c] = acc;
    }
}

// ---------------- launch -----------------------------------------------------
extern "C" void kernel_launch(void* const* d_in, const int* in_sizes, int n_in,
                              void* d_out, int out_size) {
    const float* x      = (const float*)d_in[0];
    const void*  edges  = d_in[1];
    const void*  mask   = d_in[2];
    const float* W1     = (const float*)d_in[3];
    const float* a_src1 = (const float*)d_in[4];
    const float* a_dst1 = (const float*)d_in[5];
    const float* b1     = (const float*)d_in[6];
    const float* W2     = (const float*)d_in[7];
    const float* a_src2 = (const float*)d_in[8];
    const float* a_dst2 = (const float*)d_in[9];
    const float* b2     = (const float*)d_in[10];
    const float* fc1_w  = (const float*)d_in[11];
    const float* fc1_b  = (const float*)d_in[12];
    const float* fc2_w  = (const float*)d_in[13];
    const float* fc2_b  = (const float*)d_in[14];
    float* out = (float*)d_out;

    __half* g_hh_p;   cudaGetSymbolAddress((void**)&g_hh_p, g_hh);
    float* g_out1_p;  cudaGetSymbolAddress((void**)&g_out1_p, g_out1);
    float* g_out2_p;  cudaGetSymbolAddress((void**)&g_out2_p, g_out2);

    const int smem128 = 2 * 64 * 128 + 2 * 64 * 256 + 2 * 128 * 4 + 64 * 2 * 4;   // 50688
    const int smem64  = 2 * 128 * 128 + 2 * 64 * 128 + 2 * 64 * 4 + 128 * 2 * 4;  // 50688
    const int smemFc  = (64 * 128 + 128 * 12 + FCNPB * 64 + FCNPB * 128) * 4;     // 63488
    cudaFuncSetAttribute(mma_gemm_kernel<128>, cudaFuncAttributeMaxDynamicSharedMemorySize, smem128);
    cudaFuncSetAttribute(mma_gemm_kernel<64>,  cudaFuncAttributeMaxDynamicSharedMemorySize, smem64);
    cudaFuncSetAttribute(fc_kernel, cudaFuncAttributeMaxDynamicSharedMemorySize, smemFc);

    const int warpBlocks = (NN * 32 + 255) / 256;

    // ---- side stream for the CSR chain (independent of gemm1) ----
    // Host-side objects only (no device memory); intentionally leaked —
    // kernel_launch runs twice (correctness + capture), not per-replay.
    cudaStream_t s2;
    cudaStreamCreateWithFlags(&s2, cudaStreamNonBlocking);
    cudaEvent_t eFork, eJoin;
    cudaEventCreateWithFlags(&eFork, cudaEventDisableTiming);
    cudaEventCreateWithFlags(&eJoin, cudaEventDisableTiming);

    // fork: CSR chain on s2, gemm1 on the main stream, join before agg1
    cudaEventRecord(eFork, 0);
    cudaStreamWaitEvent(s2, eFork, 0);
    convert_hist_kernel<<<(EE + MM + 255) / 256, 256, 0, s2>>>(edges, mask);
    scan1_kernel<<<NB1, 1024, 0, s2>>>();
    scan3_kernel<<<(NN + 255) / 256, 256, 0, s2>>>();
    scatter_kernel<<<(ETOT + 255) / 256, 256, 0, s2>>>(edges);
    cudaEventRecord(eJoin, s2);

    mma_gemm_kernel<128><<<(NN + 63) / 64, 256, smem128>>>(x, W1, a_src1, a_dst1, g_hh_p, NN);

    cudaStreamWaitEvent(0, eJoin, 0);
    agg_kernel<H1D><<<warpBlocks, 256>>>(g_hh_p, b1, g_out1_p);

    mma_gemm_kernel<64><<<(NN + 127) / 128, 256, smem64>>>(g_out1_p, W2, a_src2, a_dst2, g_hh_p, NN);
    agg_kernel<H2D><<<warpBlocks, 256>>>(g_hh_p, b2, g_out2_p);

    fc_kernel<<<MM / FCNPB, 256, smemFc>>>(g_out2_p, fc1_w, fc1_b, fc2_w, fc2_b, out);
}

// round 14
// speedup vs baseline: 1.0806x; 1.0678x over previous
#include <cuda_runtime.h>
#include <cuda_fp16.h>
#include <cstdint>

#define NN 100000
#define EE 1600000
#define ETOT (EE + NN)
#define FIN 128
#define H1D 128
#define H2D 64
#define FC1D 128
#define NCLS 10
#define MM 20000
#define SLOPE 0.2f
#define NB1 ((NN + 1023) / 1024)

// ---------------- scratch (device globals; no allocations allowed) ----------
__device__ int g_maskbuf[MM];
__device__ int g_cnt[NN];                       // zero-init; re-zeroed by scatter
__device__ int g_rowptr[NN + 1];
__device__ int g_cursor[NN];
__device__ int g_col[ETOT];
__device__ int g_bsum[NB1];
__device__ __half g_hh[(size_t)NN * H1D];       // fp16 h (for gather)
__device__ float g_out1[(size_t)NN * H1D];
__device__ float g_out2[(size_t)NN * H2D];
__device__ float g_as[NN];
__device__ float g_ad[NN];

// ---------------- mma helpers (sm_80-portable HMMA path) ---------------------
__device__ __forceinline__ uint32_t smem_to_u32(const void* p) {
    uint32_t a;
    asm("{ .reg .u64 t; cvta.to.shared.u64 t, %1; cvt.u32.u64 %0, t; }" : "=r"(a) : "l"(p));
    return a;
}
__device__ __forceinline__ void ldsm_x4(uint32_t* r, uint32_t addr) {
    asm volatile("ldmatrix.sync.aligned.m8n8.x4.shared.b16 {%0,%1,%2,%3}, [%4];"
        : "=r"(r[0]), "=r"(r[1]), "=r"(r[2]), "=r"(r[3]) : "r"(addr));
}
__device__ __forceinline__ void ldsm_x4_t(uint32_t* r, uint32_t addr) {
    asm volatile("ldmatrix.sync.aligned.m8n8.x4.trans.shared.b16 {%0,%1,%2,%3}, [%4];"
        : "=r"(r[0]), "=r"(r[1]), "=r"(r[2]), "=r"(r[3]) : "r"(addr));
}
__device__ __forceinline__ void mma_f16(float* c, const uint32_t* a, uint32_t b0, uint32_t b1) {
    asm volatile(
        "mma.sync.aligned.m16n8k16.row.col.f32.f16.f16.f32 "
        "{%0,%1,%2,%3}, {%4,%5,%6,%7}, {%8,%9}, {%0,%1,%2,%3};"
        : "+f"(c[0]), "+f"(c[1]), "+f"(c[2]), "+f"(c[3])
        : "r"(a[0]), "r"(a[1]), "r"(a[2]), "r"(a[3]), "r"(b0), "r"(b1));
}
__device__ __forceinline__ uint32_t pack2h(float x, float y) {
    __half2 h = __floats2half2_rn(x, y);
    return *reinterpret_cast<uint32_t*>(&h);
}
__device__ __forceinline__ bool edges_is64(const void* edges) {
    const int* q = (const int*)edges;
    return (q[1] | q[3] | q[5] | q[7] | q[9] | q[11] | q[13] | q[15]) == 0;
}

// ---------------- CSR build ---------------------------------------------------
__global__ void convert_hist_kernel(const void* edges, const void* mask) {
    int i = blockIdx.x * blockDim.x + threadIdx.x;
    bool is64 = edges_is64(edges);
    if (i < EE) {
        int d = is64 ? (int)((const long long*)edges)[EE + i]
                     : ((const int*)edges)[EE + i];
        atomicAdd(&g_cnt[d], 1);
    } else if (i < EE + MM) {
        int j = i - EE;
        g_maskbuf[j] = is64 ? (int)((const long long*)mask)[j]
                            : ((const int*)mask)[j];
    }
}

__global__ void scan1_kernel() {
    __shared__ int sh[1024];
    int t = threadIdx.x;
    int gid = blockIdx.x * 1024 + t;
    int v = (gid < NN) ? (g_cnt[gid] + 1) : 0;   // +1 = self loop
    sh[t] = v;
    __syncthreads();
    for (int off = 1; off < 1024; off <<= 1) {
        int tv = (t >= off) ? sh[t - off] : 0;
        __syncthreads();
        sh[t] += tv;
        __syncthreads();
    }
    if (gid < NN) g_rowptr[gid] = sh[t] - v;
    if (t == 1023) g_bsum[blockIdx.x] = sh[1023];
}

__global__ void scan3_kernel() {
    __shared__ int sh[256];
    int t = threadIdx.x;
    int blk = (blockIdx.x * 256) >> 10;
    sh[t] = (t < blk) ? g_bsum[t] : 0;
    __syncthreads();
    for (int off = 128; off; off >>= 1) {
        if (t < off) sh[t] += sh[t + off];
        __syncthreads();
    }
    int offset = sh[0];
    int gid = blockIdx.x * 256 + t;
    if (gid < NN) {
        int r = g_rowptr[gid] + offset;
        g_rowptr[gid] = r;
        g_cursor[gid] = r;
    }
    if (gid == 0) g_rowptr[NN] = ETOT;
}

__global__ void scatter_kernel(const void* edges) {
    int i = blockIdx.x * blockDim.x + threadIdx.x;
    if (i >= ETOT) return;
    if (i < NN) g_cnt[i] = 0;                    // cleanup for next replay
    int s, d;
    if (i < EE) {
        if (edges_is64(edges)) {
            const long long* e = (const long long*)edges;
            s = (int)e[i];
            d = (int)e[EE + i];
        } else {
            const int* e = (const int*)edges;
            s = e[i];
            d = e[EE + i];
        }
    } else {
        s = d = i - EE;
    }
    int pos = atomicAdd(&g_cursor[d], 1);
    g_col[pos] = s;
}

// ---------------- HMMA fp16 2-pass GEMM + fused alpha, fp16 output -----------
// A = Ah + Al (fp16 split, ~exact to 2^-22); B rounded once to fp16.
// D = Ah*B + Al*B (fp32 acc). 256 threads / 8 warps, 2 CTAs/SM,
// CTA tile AROWS x NOUT, warp tile 16x64, K staged in two 64-chunks.
template <int NOUT>
__global__ __launch_bounds__(256, 2)
void mma_gemm_kernel(const float* __restrict__ A, const float* __restrict__ W,
                     const float* __restrict__ a_src, const float* __restrict__ a_dst,
                     __half* __restrict__ Ch, int nrows) {
    extern __shared__ char smem[];
    constexpr int AROWS = (NOUT == 128) ? 64 : 128;
    constexpr int ROWB = NOUT * 2;               // bytes per B smem k-row
    constexpr int OFF_AH = 0;                    // AROWS x 64 fp16 (128B rows)
    constexpr int OFF_AL = AROWS * 128;
    constexpr int OFF_B  = 2 * AROWS * 128;      // 64 k-rows x NOUT fp16
    constexpr int OFF_SA = OFF_B + 64 * ROWB;
    constexpr int OFF_SAL = OFF_SA + 2 * NOUT * 4;

    const int tid = threadIdx.x;
    const int wid = tid >> 5, lane = tid & 31;
    const int row0 = blockIdx.x * AROWS;
    const uint32_t sbase = smem_to_u32(smem);
    float* sa = (float*)(smem + OFF_SA);
    float* sd = sa + NOUT;
    float* sal = (float*)(smem + OFF_SAL);

    if (tid < NOUT) {
        sa[tid] = a_src[tid];
        sd[tid] = a_dst[tid];
    }
    if (tid < AROWS * 2) sal[tid] = 0.f;

    // warp tiling: 16x64 warp tiles
    const int m0w = (NOUT == 128) ? (wid >> 1) * 16 : wid * 16;
    const int wn  = (NOUT == 128) ? (wid & 1) * 64 : 0;

    float acc[8][4];
#pragma unroll
    for (int nt = 0; nt < 8; nt++)
#pragma unroll
        for (int q = 0; q < 4; q++) acc[nt][q] = 0.f;

    const int a_row = lane & 15;
    const int a_cadd = lane >> 4;
    const int b_row = lane & 15;
    const int b_cadd = lane >> 4;

#pragma unroll
    for (int c = 0; c < 2; c++) {
        if (c) __syncthreads();                  // all warps done with chunk 0
        // ---- stage A chunk [AROWS x 64] fp32 -> fp16 hi/lo ----
        constexpr int AITER = AROWS * 16 / 256;
#pragma unroll
        for (int it = 0; it < AITER; it++) {
            int idx4 = tid + it * 256;
            int r = idx4 >> 4;
            int k4 = (idx4 & 15) * 4;
            int gr = row0 + r;
            float4 v = (gr < nrows) ? *(const float4*)&A[(size_t)gr * 128 + c * 64 + k4]
                                    : make_float4(0.f, 0.f, 0.f, 0.f);
            float hx = __half2float(__float2half_rn(v.x));
            float hy = __half2float(__float2half_rn(v.y));
            float hz = __half2float(__float2half_rn(v.z));
            float hw = __half2float(__float2half_rn(v.w));
            uint2 uh = make_uint2(pack2h(v.x, v.y), pack2h(v.z, v.w));
            uint2 ul = make_uint2(pack2h(v.x - hx, v.y - hy), pack2h(v.z - hz, v.w - hw));
            uint32_t off = (uint32_t)r * 128 + ((((k4 >> 3) ^ (r & 7)) << 4) + (k4 & 7) * 2);
            *(uint2*)(smem + OFF_AH + off) = uh;
            *(uint2*)(smem + OFF_AL + off) = ul;
        }
        // ---- stage B chunk [64 x NOUT] fp32 -> fp16 ----
        constexpr int QPR = NOUT / 4;
        constexpr int BITER = 64 * QPR / 256;
#pragma unroll
        for (int it = 0; it < BITER; it++) {
            int idx = tid + it * 256;
            int kk = idx / QPR;
            int n4 = (idx % QPR) * 4;
            float4 v = *(const float4*)&W[(size_t)(c * 64 + kk) * NOUT + n4];
            uint2 uh = make_uint2(pack2h(v.x, v.y), pack2h(v.z, v.w));
            uint32_t off = (uint32_t)kk * ROWB + ((((n4 >> 3) ^ (kk & 7)) << 4) + (n4 & 7) * 2);
            *(uint2*)(smem + OFF_B + off) = uh;
        }
        __syncthreads();

        // ---- 4 k-steps of 16 within this chunk ----
#pragma unroll
        for (int ks = 0; ks < 4; ks++) {
            uint32_t ah[4], al[4];
            {
                int r = m0w + a_row;
                int chunk = ks * 2 + a_cadd;
                uint32_t off = (uint32_t)r * 128 + (((chunk ^ (r & 7)) & 7) << 4);
                ldsm_x4(ah, sbase + OFF_AH + off);
                ldsm_x4(al, sbase + OFF_AL + off);
            }
#pragma unroll
            for (int p = 0; p < 4; p++) {
                int nbase = wn + p * 16;
                int r = ks * 16 + b_row;
                int chunkb = (nbase >> 3) + b_cadd;
                uint32_t off = (uint32_t)r * ROWB + (((chunkb ^ (r & 7)) & (ROWB / 16 - 1)) << 4);
                uint32_t bf[4];
                ldsm_x4_t(bf, sbase + OFF_B + off);
                mma_f16(acc[2 * p],     ah, bf[0], bf[1]);
                mma_f16(acc[2 * p + 1], ah, bf[2], bf[3]);
                mma_f16(acc[2 * p],     al, bf[0], bf[1]);
                mma_f16(acc[2 * p + 1], al, bf[2], bf[3]);
            }
        }
    }

    // ---- epilogue: fp16 store + fused alpha reduction ----
    const int group = lane >> 2;
    const int tc = (lane & 3) * 2;
    {
        int r0 = row0 + m0w + group;
        int r1 = r0 + 8;
        float s0 = 0.f, d0 = 0.f, s1 = 0.f, d1 = 0.f;
#pragma unroll
        for (int nt = 0; nt < 8; nt++) {
            int col = wn + nt * 8 + tc;
            float va0 = sa[col], va1 = sa[col + 1];
            float vd0 = sd[col], vd1 = sd[col + 1];
            s0 += acc[nt][0] * va0 + acc[nt][1] * va1;
            d0 += acc[nt][0] * vd0 + acc[nt][1] * vd1;
            s1 += acc[nt][2] * va0 + acc[nt][3] * va1;
            d1 += acc[nt][2] * vd0 + acc[nt][3] * vd1;
            if (r0 < nrows)
                *(__half2*)&Ch[(size_t)r0 * NOUT + col] = __floats2half2_rn(acc[nt][0], acc[nt][1]);
            if (r1 < nrows)
                *(__half2*)&Ch[(size_t)r1 * NOUT + col] = __floats2half2_rn(acc[nt][2], acc[nt][3]);
        }
#pragma unroll
        for (int m = 1; m <= 2; m <<= 1) {
            s0 += __shfl_xor_sync(0xffffffffu, s0, m);
            d0 += __shfl_xor_sync(0xffffffffu, d0, m);
            s1 += __shfl_xor_sync(0xffffffffu, s1, m);
            d1 += __shfl_xor_sync(0xffffffffu, d1, m);
        }
        if ((lane & 3) == 0) {
            int rl = m0w + group;
            atomicAdd(&sal[rl * 2], s0);
            atomicAdd(&sal[rl * 2 + 1], d0);
            atomicAdd(&sal[(rl + 8) * 2], s1);
            atomicAdd(&sal[(rl + 8) * 2 + 1], d1);
        }
    }
    __syncthreads();
    if (tid < AROWS) {
        int row = row0 + tid;
        if (row < nrows) {
            g_as[row] = sal[tid * 2];
            g_ad[row] = sal[tid * 2 + 1];
        }
    }
}

// ---------------- fused softmax + gather: warp per node, fp16 h, 4-unroll ----
template <int F>
__global__ void agg_kernel(const __half* __restrict__ hh, const float* __restrict__ bias,
                           float* __restrict__ out) {
    constexpr int V = F / 32;
    int node = (blockIdx.x * blockDim.x + threadIdx.x) >> 5;
    int lane = threadIdx.x & 31;
    if (node >= NN) return;
    int idx = g_rowptr[node];
    const int end = g_rowptr[node + 1];
    const float adv = g_ad[node];
    float mm = g_as[node] + adv;
    const float m = (mm > 0.f) ? mm : SLOPE * mm;
    float Z = 0.f;
    float acc[V];
#pragma unroll
    for (int j = 0; j < V; j++) acc[j] = 0.f;

    for (; idx + 4 <= end; idx += 4) {
        int s0 = g_col[idx];
        int s1 = g_col[idx + 1];
        int s2 = g_col[idx + 2];
        int s3 = g_col[idx + 3];
        float e0 = g_as[s0] + adv;
        float e1 = g_as[s1] + adv;
        float e2 = g_as[s2] + adv;
        float e3 = g_as[s3] + adv;
        e0 = (e0 > 0.f) ? e0 : SLOPE * e0;
        e1 = (e1 > 0.f) ? e1 : SLOPE * e1;
        e2 = (e2 > 0.f) ? e2 : SLOPE * e2;
        e3 = (e3 > 0.f) ? e3 : SLOPE * e3;
        float w0 = __expf(e0 - m);
        float w1 = __expf(e1 - m);
        float w2 = __expf(e2 - m);
        float w3 = __expf(e3 - m);
        Z += (w0 + w1) + (w2 + w3);
        if (V == 4) {
            uint2 u0 = *(const uint2*)&hh[(size_t)s0 * F + lane * 4];
            uint2 u1 = *(const uint2*)&hh[(size_t)s1 * F + lane * 4];
            uint2 u2 = *(const uint2*)&hh[(size_t)s2 * F + lane * 4];
            uint2 u3 = *(const uint2*)&hh[(size_t)s3 * F + lane * 4];
            float2 a0 = __half22float2(*(const __half2*)&u0.x);
            float2 b0 = __half22float2(*(const __half2*)&u0.y);
            float2 a1 = __half22float2(*(const __half2*)&u1.x);
            float2 b1 = __half22float2(*(const __half2*)&u1.y);
            float2 a2 = __half22float2(*(const __half2*)&u2.x);
            float2 b2 = __half22float2(*(const __half2*)&u2.y);
            float2 a3 = __half22float2(*(const __half2*)&u3.x);
            float2 b3 = __half22float2(*(const __half2*)&u3.y);
            acc[0] += (w0 * a0.x + w1 * a1.x) + (w2 * a2.x + w3 * a3.x);
            acc[1] += (w0 * a0.y + w1 * a1.y) + (w2 * a2.y + w3 * a3.y);
            acc[2] += (w0 * b0.x + w1 * b1.x) + (w2 * b2.x + w3 * b3.x);
            acc[3] += (w0 * b0.y + w1 * b1.y) + (w2 * b2.y + w3 * b3.y);
        } else {
            float2 a0 = __half22float2(*(const __half2*)&hh[(size_t)s0 * F + lane * 2]);
            float2 a1 = __half22float2(*(const __half2*)&hh[(size_t)s1 * F + lane * 2]);
            float2 a2 = __half22float2(*(const __half2*)&hh[(size_t)s2 * F + lane * 2]);
            float2 a3 = __half22float2(*(const __half2*)&hh[(size_t)s3 * F + lane * 2]);
            acc[0] += (w0 * a0.x + w1 * a1.x) + (w2 * a2.x + w3 * a3.x);
            acc[1] += (w0 * a0.y + w1 * a1.y) + (w2 * a2.y + w3 * a3.y);
        }
    }
    for (; idx < end; idx++) {
        int s0 = g_col[idx];
        float e0 = g_as[s0] + adv;
        e0 = (e0 > 0.f) ? e0 : SLOPE * e0;
        float w0 = __expf(e0 - m);
        Z += w0;
        if (V == 4) {
            uint2 u0 = *(const uint2*)&hh[(size_t)s0 * F + lane * 4];
            float2 a0 = __half22float2(*(const __half2*)&u0.x);
            float2 b0 = __half22float2(*(const __half2*)&u0.y);
            acc[0] += w0 * a0.x; acc[1] += w0 * a0.y;
            acc[2] += w0 * b0.x; acc[3] += w0 * b0.y;
        } else {
            float2 a0 = __half22float2(*(const __half2*)&hh[(size_t)s0 * F + lane * 2]);
            acc[0] += w0 * a0.x; acc[1] += w0 * a0.y;
        }
    }

    const float iz = 1.f / Z;
    if (V == 4) {
        float4 b4 = *(const float4*)&bias[lane * 4];
        float4 o;
        o.x = fmaxf(acc[0] * iz + b4.x, 0.f);
        o.y = fmaxf(acc[1] * iz + b4.y, 0.f);
        o.z = fmaxf(acc[2] * iz + b4.z, 0.f);
        o.w = fmaxf(acc[3] * iz + b4.w, 0.f);
        *(float4*)&out[(size_t)node * F + lane * 4] = o;
    } else {
        float2 b2 = *(const float2*)&bias[lane * 2];
        float2 o;
        o.x = fmaxf(acc[0] * iz + b2.x, 0.f);
        o.y = fmaxf(acc[1] * iz + b2.y, 0.f);
        *(float2*)&out[(size_t)node * F + lane * 2] = o;
    }
}

// ---------------- FC head: 32 mask-nodes per block, weights staged in smem ---
#define FCNPB 32
__global__ __launch_bounds__(256)
void fc_kernel(const float* __restrict__ feat,
               const float* __restrict__ w1, const float* __restrict__ b1,
               const float* __restrict__ w2, const float* __restrict__ b2,
               float* __restrict__ out) {
    extern __shared__ float sm[];
    float* sw1 = sm;
    float* sw2 = sw1 + 64 * 128;
    float* sf  = sw2 + 128 * 12;
    float* sz  = sf + FCNPB * 64;

    const int tid = threadIdx.x;
    const int mi0 = blockIdx.x * FCNPB;

#pragma unroll
    for (int it = 0; it < 8; it++) {
        int i4 = tid + it * 256;
        *(float4*)&sw1[i4 * 4] = *(const float4*)&w1[i4 * 4];
    }
    for (int i = tid; i < 128 * NCLS; i += 256)
        sw2[(i / NCLS) * 12 + (i % NCLS)] = w2[i];
#pragma unroll
    for (int it = 0; it < 2; it++) {
        int i4 = tid + it * 256;
        int n = i4 >> 4;
        int c4 = (i4 & 15) * 4;
        int node = g_maskbuf[mi0 + n];
        *(float4*)&sf[n * 64 + c4] = *(const float4*)&feat[(size_t)node * H2D + c4];
    }
    __syncthreads();

#pragma unroll
    for (int it = 0; it < 16; it++) {
        int oi = tid + it * 256;
        int n = oi >> 7;
        int t = oi & 127;
        float acc = b1[t];
#pragma unroll
        for (int k = 0; k < 64; k++)
            acc += sf[n * 64 + k] * sw1[k * 128 + t];
        sz[n * 128 + t] = fmaxf(acc, 0.f);
    }
    __syncthreads();

    for (int oi = tid; oi < FCNPB * NCLS; oi += 256) {
        int n = oi / NCLS;
        int c = oi % NCLS;
        float acc = b2[c];
#pragma unroll
        for (int j = 0; j < 128; j++)
            acc += sz[n * 128 + j] * sw2[j * 12 + c];
        out[(size_t)(mi0 + n) * NCLS + c] = acc;
    }
}

// ---------------- launch -----------------------------------------------------
extern "C" void kernel_launch(void* const* d_in, const int* in_sizes, int n_in,
                              void* d_out, int out_size) {
    const float* x      = (const float*)d_in[0];
    const void*  edges  = d_in[1];
    const void*  mask   = d_in[2];
    const float* W1     = (const float*)d_in[3];
    const float* a_src1 = (const float*)d_in[4];
    const float* a_dst1 = (const float*)d_in[5];
    const float* b1     = (const float*)d_in[6];
    const float* W2     = (const float*)d_in[7];
    const float* a_src2 = (const float*)d_in[8];
    const float* a_dst2 = (const float*)d_in[9];
    const float* b2     = (const float*)d_in[10];
    const float* fc1_w  = (const float*)d_in[11];
    const float* fc1_b  = (const float*)d_in[12];
    const float* fc2_w  = (const float*)d_in[13];
    const float* fc2_b  = (const float*)d_in[14];
    float* out = (float*)d_out;

    __half* g_hh_p;   cudaGetSymbolAddress((void**)&g_hh_p, g_hh);
    float* g_out1_p;  cudaGetSymbolAddress((void**)&g_out1_p, g_out1);
    float* g_out2_p;  cudaGetSymbolAddress((void**)&g_out2_p, g_out2);

    // smem: A 2*AROWS*128 + B 64*ROWB + sa/sd + sal
    const int smem128 = 2 * 64 * 128 + 64 * 256 + 2 * 128 * 4 + 64 * 2 * 4;    // 34304
    const int smem64  = 2 * 128 * 128 + 64 * 128 + 2 * 64 * 4 + 128 * 2 * 4;   // 42496
    const int smemFc  = (64 * 128 + 128 * 12 + FCNPB * 64 + FCNPB * 128) * 4;  // 63488
    cudaFuncSetAttribute(mma_gemm_kernel<128>, cudaFuncAttributeMaxDynamicSharedMemorySize, smem128);
    cudaFuncSetAttribute(mma_gemm_kernel<64>,  cudaFuncAttributeMaxDynamicSharedMemorySize, smem64);
    cudaFuncSetAttribute(fc_kernel, cudaFuncAttributeMaxDynamicSharedMemorySize, smemFc);

    const int warpBlocks = (NN * 32 + 255) / 256;

    // single-stream R11 schedule (stream fork measured as a regression)
    convert_hist_kernel<<<(EE + MM + 255) / 256, 256>>>(edges, mask);
    scan1_kernel<<<NB1, 1024>>>();
    scan3_kernel<<<(NN + 255) / 256, 256>>>();
    mma_gemm_kernel<128><<<(NN + 63) / 64, 256, smem128>>>(x, W1, a_src1, a_dst1, g_hh_p, NN);
    scatter_kernel<<<(ETOT + 255) / 256, 256>>>(edges);
    agg_kernel<H1D><<<warpBlocks, 256>>>(g_hh_p, b1, g_out1_p);

    mma_gemm_kernel<64><<<(NN + 127) / 128, 256, smem64>>>(g_out1_p, W2, a_src2, a_dst2, g_hh_p, NN);
    agg_kernel<H2D><<<warpBlocks, 256>>>(g_hh_p, b2, g_out2_p);

    fc_kernel<<<MM / FCNPB, 256, smemFc>>>(g_out2_p, fc1_w, fc1_b, fc2_w, fc2_b, out);
}

// round 15
// speedup vs baseline: 1.1118x; 1.0288x over previous
#include <cuda_runtime.h>
#include <cuda_fp16.h>
#include <cstdint>

#define NN 100000
#define EE 1600000
#define ETOT (EE + NN)
#define FIN 128
#define H1D 128
#define H2D 64
#define FC1D 128
#define NCLS 10
#define MM 20000
#define SLOPE 0.2f
#define NB1 ((NN + 1023) / 1024)

// ---------------- scratch (device globals; no allocations allowed) ----------
__device__ int g_maskbuf[MM];
__device__ int g_cnt[NN];                       // zero-init; re-zeroed by scatter
__device__ int g_rank[EE];                      // per-edge arrival rank at its dst
__device__ int g_rowptr[NN + 1];
__device__ int g_col[ETOT];
__device__ int g_bsum[NB1];
__device__ __half g_hh[(size_t)NN * H1D];       // fp16 h (for gather)
__device__ float g_out1[(size_t)NN * H1D];
__device__ float g_out2[(size_t)NN * H2D];
__device__ float g_as[NN];
__device__ float g_ad[NN];

// ---------------- mma helpers (sm_80-portable HMMA path) ---------------------
__device__ __forceinline__ uint32_t smem_to_u32(const void* p) {
    uint32_t a;
    asm("{ .reg .u64 t; cvta.to.shared.u64 t, %1; cvt.u32.u64 %0, t; }" : "=r"(a) : "l"(p));
    return a;
}
__device__ __forceinline__ void ldsm_x4(uint32_t* r, uint32_t addr) {
    asm volatile("ldmatrix.sync.aligned.m8n8.x4.shared.b16 {%0,%1,%2,%3}, [%4];"
        : "=r"(r[0]), "=r"(r[1]), "=r"(r[2]), "=r"(r[3]) : "r"(addr));
}
__device__ __forceinline__ void ldsm_x4_t(uint32_t* r, uint32_t addr) {
    asm volatile("ldmatrix.sync.aligned.m8n8.x4.trans.shared.b16 {%0,%1,%2,%3}, [%4];"
        : "=r"(r[0]), "=r"(r[1]), "=r"(r[2]), "=r"(r[3]) : "r"(addr));
}
__device__ __forceinline__ void mma_f16(float* c, const uint32_t* a, uint32_t b0, uint32_t b1) {
    asm volatile(
        "mma.sync.aligned.m16n8k16.row.col.f32.f16.f16.f32 "
        "{%0,%1,%2,%3}, {%4,%5,%6,%7}, {%8,%9}, {%0,%1,%2,%3};"
        : "+f"(c[0]), "+f"(c[1]), "+f"(c[2]), "+f"(c[3])
        : "r"(a[0]), "r"(a[1]), "r"(a[2]), "r"(a[3]), "r"(b0), "r"(b1));
}
__device__ __forceinline__ uint32_t pack2h(float x, float y) {
    __half2 h = __floats2half2_rn(x, y);
    return *reinterpret_cast<uint32_t*>(&h);
}
__device__ __forceinline__ bool edges_is64(const void* edges) {
    const int* q = (const int*)edges;
    return (q[1] | q[3] | q[5] | q[7] | q[9] | q[11] | q[13] | q[15]) == 0;
}

// ---------------- CSR build ---------------------------------------------------
// histogram dst counts, record per-edge rank; convert mask
__global__ void convert_hist_kernel(const void* edges, const void* mask) {
    int i = blockIdx.x * blockDim.x + threadIdx.x;
    bool is64 = edges_is64(edges);
    if (i < EE) {
        int d = is64 ? (int)((const long long*)edges)[EE + i]
                     : ((const int*)edges)[EE + i];
        g_rank[i] = atomicAdd(&g_cnt[d], 1);
    } else if (i < EE + MM) {
        int j = i - EE;
        g_maskbuf[j] = is64 ? (int)((const long long*)mask)[j]
                            : ((const int*)mask)[j];
    }
}

__global__ void scan1_kernel() {
    __shared__ int sh[1024];
    int t = threadIdx.x;
    int gid = blockIdx.x * 1024 + t;
    int v = (gid < NN) ? (g_cnt[gid] + 1) : 0;   // +1 = self loop
    sh[t] = v;
    __syncthreads();
    for (int off = 1; off < 1024; off <<= 1) {
        int tv = (t >= off) ? sh[t - off] : 0;
        __syncthreads();
        sh[t] += tv;
        __syncthreads();
    }
    if (gid < NN) g_rowptr[gid] = sh[t] - v;
    if (t == 1023) g_bsum[blockIdx.x] = sh[1023];
}

__global__ void scan3_kernel() {
    __shared__ int sh[256];
    int t = threadIdx.x;
    int blk = (blockIdx.x * 256) >> 10;
    sh[t] = (t < blk) ? g_bsum[t] : 0;
    __syncthreads();
    for (int off = 128; off; off >>= 1) {
        if (t < off) sh[t] += sh[t + off];
        __syncthreads();
    }
    int offset = sh[0];
    int gid = blockIdx.x * 256 + t;
    if (gid < NN) g_rowptr[gid] += offset;
    if (gid == 0) g_rowptr[NN] = ETOT;
}

// scatter edges into CSR using precomputed ranks (NO atomics); re-zero g_cnt.
// slot rowptr[d] holds the self loop; edges land at rowptr[d] + 1 + rank.
__global__ void scatter_kernel(const void* edges) {
    int i = blockIdx.x * blockDim.x + threadIdx.x;
    if (i >= ETOT) return;
    if (i < NN) g_cnt[i] = 0;                    // cleanup for next replay
    if (i < EE) {
        int s, d;
        if (edges_is64(edges)) {
            const long long* e = (const long long*)edges;
            s = (int)e[i];
            d = (int)e[EE + i];
        } else {
            const int* e = (const int*)edges;
            s = e[i];
            d = e[EE + i];
        }
        g_col[g_rowptr[d] + 1 + g_rank[i]] = s;
    } else {
        int n = i - EE;
        g_col[g_rowptr[n]] = n;                  // self loop
    }
}

// ---------------- HMMA fp16 single-pass GEMM + fused alpha, fp16 output ------
// A and B both rounded once to fp16 (validated RMS error model: ~2.8e-4 each).
// 256 threads / 8 warps, 2 CTAs/SM, CTA tile AROWS x NOUT, warp tile 16x64,
// K staged in two 64-chunks.
template <int NOUT>
__global__ __launch_bounds__(256, 2)
void mma_gemm_kernel(const float* __restrict__ A, const float* __restrict__ W,
                     const float* __restrict__ a_src, const float* __restrict__ a_dst,
                     __half* __restrict__ Ch, int nrows) {
    extern __shared__ char smem[];
    constexpr int AROWS = (NOUT == 128) ? 64 : 128;
    constexpr int ROWB = NOUT * 2;               // bytes per B smem k-row
    constexpr int OFF_A = 0;                     // AROWS x 64 fp16 (128B rows)
    constexpr int OFF_B = AROWS * 128;           // 64 k-rows x NOUT fp16
    constexpr int OFF_SA = OFF_B + 64 * ROWB;
    constexpr int OFF_SAL = OFF_SA + 2 * NOUT * 4;

    const int tid = threadIdx.x;
    const int wid = tid >> 5, lane = tid & 31;
    const int row0 = blockIdx.x * AROWS;
    const uint32_t sbase = smem_to_u32(smem);
    float* sa = (float*)(smem + OFF_SA);
    float* sd = sa + NOUT;
    float* sal = (float*)(smem + OFF_SAL);

    if (tid < NOUT) {
        sa[tid] = a_src[tid];
        sd[tid] = a_dst[tid];
    }
    if (tid < AROWS * 2) sal[tid] = 0.f;

    // warp tiling: 16x64 warp tiles
    const int m0w = (NOUT == 128) ? (wid >> 1) * 16 : wid * 16;
    const int wn  = (NOUT == 128) ? (wid & 1) * 64 : 0;

    float acc[8][4];
#pragma unroll
    for (int nt = 0; nt < 8; nt++)
#pragma unroll
        for (int q = 0; q < 4; q++) acc[nt][q] = 0.f;

    const int a_row = lane & 15;
    const int a_cadd = lane >> 4;
    const int b_row = lane & 15;
    const int b_cadd = lane >> 4;

#pragma unroll
    for (int c = 0; c < 2; c++) {
        if (c) __syncthreads();                  // all warps done with chunk 0
        // ---- stage A chunk [AROWS x 64] fp32 -> fp16 ----
        constexpr int AITER = AROWS * 16 / 256;
#pragma unroll
        for (int it = 0; it < AITER; it++) {
            int idx4 = tid + it * 256;
            int r = idx4 >> 4;
            int k4 = (idx4 & 15) * 4;
            int gr = row0 + r;
            float4 v = (gr < nrows) ? *(const float4*)&A[(size_t)gr * 128 + c * 64 + k4]
                                    : make_float4(0.f, 0.f, 0.f, 0.f);
            uint2 uh = make_uint2(pack2h(v.x, v.y), pack2h(v.z, v.w));
            uint32_t off = (uint32_t)r * 128 + ((((k4 >> 3) ^ (r & 7)) << 4) + (k4 & 7) * 2);
            *(uint2*)(smem + OFF_A + off) = uh;
        }
        // ---- stage B chunk [64 x NOUT] fp32 -> fp16 ----
        constexpr int QPR = NOUT / 4;
        constexpr int BITER = 64 * QPR / 256;
#pragma unroll
        for (int it = 0; it < BITER; it++) {
            int idx = tid + it * 256;
            int kk = idx / QPR;
            int n4 = (idx % QPR) * 4;
            float4 v = *(const float4*)&W[(size_t)(c * 64 + kk) * NOUT + n4];
            uint2 uh = make_uint2(pack2h(v.x, v.y), pack2h(v.z, v.w));
            uint32_t off = (uint32_t)kk * ROWB + ((((n4 >> 3) ^ (kk & 7)) << 4) + (n4 & 7) * 2);
            *(uint2*)(smem + OFF_B + off) = uh;
        }
        __syncthreads();

        // ---- 4 k-steps of 16 within this chunk ----
#pragma unroll
        for (int ks = 0; ks < 4; ks++) {
            uint32_t ah[4];
            {
                int r = m0w + a_row;
                int chunk = ks * 2 + a_cadd;
                uint32_t off = (uint32_t)r * 128 + (((chunk ^ (r & 7)) & 7) << 4);
                ldsm_x4(ah, sbase + OFF_A + off);
            }
#pragma unroll
            for (int p = 0; p < 4; p++) {
                int nbase = wn + p * 16;
                int r = ks * 16 + b_row;
                int chunkb = (nbase >> 3) + b_cadd;
                uint32_t off = (uint32_t)r * ROWB + (((chunkb ^ (r & 7)) & (ROWB / 16 - 1)) << 4);
                uint32_t bf[4];
                ldsm_x4_t(bf, sbase + OFF_B + off);
                mma_f16(acc[2 * p],     ah, bf[0], bf[1]);
                mma_f16(acc[2 * p + 1], ah, bf[2], bf[3]);
            }
        }
    }

    // ---- epilogue: fp16 store + fused alpha reduction ----
    const int group = lane >> 2;
    const int tc = (lane & 3) * 2;
    {
        int r0 = row0 + m0w + group;
        int r1 = r0 + 8;
        float s0 = 0.f, d0 = 0.f, s1 = 0.f, d1 = 0.f;
#pragma unroll
        for (int nt = 0; nt < 8; nt++) {
            int col = wn + nt * 8 + tc;
            float va0 = sa[col], va1 = sa[col + 1];
            float vd0 = sd[col], vd1 = sd[col + 1];
            s0 += acc[nt][0] * va0 + acc[nt][1] * va1;
            d0 += acc[nt][0] * vd0 + acc[nt][1] * vd1;
            s1 += acc[nt][2] * va0 + acc[nt][3] * va1;
            d1 += acc[nt][2] * vd0 + acc[nt][3] * vd1;
            if (r0 < nrows)
                *(__half2*)&Ch[(size_t)r0 * NOUT + col] = __floats2half2_rn(acc[nt][0], acc[nt][1]);
            if (r1 < nrows)
                *(__half2*)&Ch[(size_t)r1 * NOUT + col] = __floats2half2_rn(acc[nt][2], acc[nt][3]);
        }
#pragma unroll
        for (int m = 1; m <= 2; m <<= 1) {
            s0 += __shfl_xor_sync(0xffffffffu, s0, m);
            d0 += __shfl_xor_sync(0xffffffffu, d0, m);
            s1 += __shfl_xor_sync(0xffffffffu, s1, m);
            d1 += __shfl_xor_sync(0xffffffffu, d1, m);
        }
        if ((lane & 3) == 0) {
            int rl = m0w + group;
            atomicAdd(&sal[rl * 2], s0);
            atomicAdd(&sal[rl * 2 + 1], d0);
            atomicAdd(&sal[(rl + 8) * 2], s1);
            atomicAdd(&sal[(rl + 8) * 2 + 1], d1);
        }
    }
    __syncthreads();
    if (tid < AROWS) {
        int row = row0 + tid;
        if (row < nrows) {
            g_as[row] = sal[tid * 2];
            g_ad[row] = sal[tid * 2 + 1];
        }
    }
}

// ---------------- fused softmax + gather: warp per node, fp16 h, 4-unroll ----
template <int F>
__global__ void agg_kernel(const __half* __restrict__ hh, const float* __restrict__ bias,
                           float* __restrict__ out) {
    constexpr int V = F / 32;
    int node = (blockIdx.x * blockDim.x + threadIdx.x) >> 5;
    int lane = threadIdx.x & 31;
    if (node >= NN) return;
    int idx = g_rowptr[node];
    const int end = g_rowptr[node + 1];
    const float adv = g_ad[node];
    float mm = g_as[node] + adv;
    const float m = (mm > 0.f) ? mm : SLOPE * mm;
    float Z = 0.f;
    float acc[V];
#pragma unroll
    for (int j = 0; j < V; j++) acc[j] = 0.f;

    for (; idx + 4 <= end; idx += 4) {
        int s0 = g_col[idx];
        int s1 = g_col[idx + 1];
        int s2 = g_col[idx + 2];
        int s3 = g_col[idx + 3];
        float e0 = g_as[s0] + adv;
        float e1 = g_as[s1] + adv;
        float e2 = g_as[s2] + adv;
        float e3 = g_as[s3] + adv;
        e0 = (e0 > 0.f) ? e0 : SLOPE * e0;
        e1 = (e1 > 0.f) ? e1 : SLOPE * e1;
        e2 = (e2 > 0.f) ? e2 : SLOPE * e2;
        e3 = (e3 > 0.f) ? e3 : SLOPE * e3;
        float w0 = __expf(e0 - m);
        float w1 = __expf(e1 - m);
        float w2 = __expf(e2 - m);
        float w3 = __expf(e3 - m);
        Z += (w0 + w1) + (w2 + w3);
        if (V == 4) {
            uint2 u0 = *(const uint2*)&hh[(size_t)s0 * F + lane * 4];
            uint2 u1 = *(const uint2*)&hh[(size_t)s1 * F + lane * 4];
            uint2 u2 = *(const uint2*)&hh[(size_t)s2 * F + lane * 4];
            uint2 u3 = *(const uint2*)&hh[(size_t)s3 * F + lane * 4];
            float2 a0 = __half22float2(*(const __half2*)&u0.x);
            float2 b0 = __half22float2(*(const __half2*)&u0.y);
            float2 a1 = __half22float2(*(const __half2*)&u1.x);
            float2 b1 = __half22float2(*(const __half2*)&u1.y);
            float2 a2 = __half22float2(*(const __half2*)&u2.x);
            float2 b2 = __half22float2(*(const __half2*)&u2.y);
            float2 a3 = __half22float2(*(const __half2*)&u3.x);
            float2 b3 = __half22float2(*(const __half2*)&u3.y);
            acc[0] += (w0 * a0.x + w1 * a1.x) + (w2 * a2.x + w3 * a3.x);
            acc[1] += (w0 * a0.y + w1 * a1.y) + (w2 * a2.y + w3 * a3.y);
            acc[2] += (w0 * b0.x + w1 * b1.x) + (w2 * b2.x + w3 * b3.x);
            acc[3] += (w0 * b0.y + w1 * b1.y) + (w2 * b2.y + w3 * b3.y);
        } else {
            float2 a0 = __half22float2(*(const __half2*)&hh[(size_t)s0 * F + lane * 2]);
            float2 a1 = __half22float2(*(const __half2*)&hh[(size_t)s1 * F + lane * 2]);
            float2 a2 = __half22float2(*(const __half2*)&hh[(size_t)s2 * F + lane * 2]);
            float2 a3 = __half22float2(*(const __half2*)&hh[(size_t)s3 * F + lane * 2]);
            acc[0] += (w0 * a0.x + w1 * a1.x) + (w2 * a2.x + w3 * a3.x);
            acc[1] += (w0 * a0.y + w1 * a1.y) + (w2 * a2.y + w3 * a3.y);
        }
    }
    for (; idx < end; idx++) {
        int s0 = g_col[idx];
        float e0 = g_as[s0] + adv;
        e0 = (e0 > 0.f) ? e0 : SLOPE * e0;
        float w0 = __expf(e0 - m);
        Z += w0;
        if (V == 4) {
            uint2 u0 = *(const uint2*)&hh[(size_t)s0 * F + lane * 4];
            float2 a0 = __half22float2(*(const __half2*)&u0.x);
            float2 b0 = __half22float2(*(const __half2*)&u0.y);
            acc[0] += w0 * a0.x; acc[1] += w0 * a0.y;
            acc[2] += w0 * b0.x; acc[3] += w0 * b0.y;
        } else {
            float2 a0 = __half22float2(*(const __half2*)&hh[(size_t)s0 * F + lane * 2]);
            acc[0] += w0 * a0.x; acc[1] += w0 * a0.y;
        }
    }

    const float iz = 1.f / Z;
    if (V == 4) {
        float4 b4 = *(const float4*)&bias[lane * 4];
        float4 o;
        o.x = fmaxf(acc[0] * iz + b4.x, 0.f);
        o.y = fmaxf(acc[1] * iz + b4.y, 0.f);
        o.z = fmaxf(acc[2] * iz + b4.z, 0.f);
        o.w = fmaxf(acc[3] * iz + b4.w, 0.f);
        *(float4*)&out[(size_t)node * F + lane * 4] = o;
    } else {
        float2 b2 = *(const float2*)&bias[lane * 2];
        float2 o;
        o.x = fmaxf(acc[0] * iz + b2.x, 0.f);
        o.y = fmaxf(acc[1] * iz + b2.y, 0.f);
        *(float2*)&out[(size_t)node * F + lane * 2] = o;
    }
}

// ---------------- FC head: 32 mask-nodes per block, weights staged in smem ---
#define FCNPB 32
__global__ __launch_bounds__(256)
void fc_kernel(const float* __restrict__ feat,
               const float* __restrict__ w1, const float* __restrict__ b1,
               const float* __restrict__ w2, const float* __restrict__ b2,
               float* __restrict__ out) {
    extern __shared__ float sm[];
    float* sw1 = sm;
    float* sw2 = sw1 + 64 * 128;
    float* sf  = sw2 + 128 * 12;
    float* sz  = sf + FCNPB * 64;

    const int tid = threadIdx.x;
    const int mi0 = blockIdx.x * FCNPB;

#pragma unroll
    for (int it = 0; it < 8; it++) {
        int i4 = tid + it * 256;
        *(float4*)&sw1[i4 * 4] = *(const float4*)&w1[i4 * 4];
    }
    for (int i = tid; i < 128 * NCLS; i += 256)
        sw2[(i / NCLS) * 12 + (i % NCLS)] = w2[i];
#pragma unroll
    for (int it = 0; it < 2; it++) {
        int i4 = tid + it * 256;
        int n = i4 >> 4;
        int c4 = (i4 & 15) * 4;
        int node = g_maskbuf[mi0 + n];
        *(float4*)&sf[n * 64 + c4] = *(const float4*)&feat[(size_t)node * H2D + c4];
    }
    __syncthreads();

#pragma unroll
    for (int it = 0; it < 16; it++) {
        int oi = tid + it * 256;
        int n = oi >> 7;
        int t = oi & 127;
        float acc = b1[t];
#pragma unroll
        for (int k = 0; k < 64; k++)
            acc += sf[n * 64 + k] * sw1[k * 128 + t];
        sz[n * 128 + t] = fmaxf(acc, 0.f);
    }
    __syncthreads();

    for (int oi = tid; oi < FCNPB * NCLS; oi += 256) {
        int n = oi / NCLS;
        int c = oi % NCLS;
        float acc = b2[c];
#pragma unroll
        for (int j = 0; j < 128; j++)
            acc += sz[n * 128 + j] * sw2[j * 12 + c];
        out[(size_t)(mi0 + n) * NCLS + c] = acc;
    }
}

// ---------------- launch -----------------------------------------------------
extern "C" void kernel_launch(void* const* d_in, const int* in_sizes, int n_in,
                              void* d_out, int out_size) {
    const float* x      = (const float*)d_in[0];
    const void*  edges  = d_in[1];
    const void*  mask   = d_in[2];
    const float* W1     = (const float*)d_in[3];
    const float* a_src1 = (const float*)d_in[4];
    const float* a_dst1 = (const float*)d_in[5];
    const float* b1     = (const float*)d_in[6];
    const float* W2     = (const float*)d_in[7];
    const float* a_src2 = (const float*)d_in[8];
    const float* a_dst2 = (const float*)d_in[9];
    const float* b2     = (const float*)d_in[10];
    const float* fc1_w  = (const float*)d_in[11];
    const float* fc1_b  = (const float*)d_in[12];
    const float* fc2_w  = (const float*)d_in[13];
    const float* fc2_b  = (const float*)d_in[14];
    float* out = (float*)d_out;

    __half* g_hh_p;   cudaGetSymbolAddress((void**)&g_hh_p, g_hh);
    float* g_out1_p;  cudaGetSymbolAddress((void**)&g_out1_p, g_out1);
    float* g_out2_p;  cudaGetSymbolAddress((void**)&g_out2_p, g_out2);

    // smem: A AROWS*128 + B 64*ROWB + sa/sd + sal
    const int smem128 = 64 * 128 + 64 * 256 + 2 * 128 * 4 + 64 * 2 * 4;        // 26112
    const int smem64  = 128 * 128 + 64 * 128 + 2 * 64 * 4 + 128 * 2 * 4;       // 26112
    const int smemFc  = (64 * 128 + 128 * 12 + FCNPB * 64 + FCNPB * 128) * 4;  // 63488
    cudaFuncSetAttribute(mma_gemm_kernel<128>, cudaFuncAttributeMaxDynamicSharedMemorySize, smem128);
    cudaFuncSetAttribute(mma_gemm_kernel<64>,  cudaFuncAttributeMaxDynamicSharedMemorySize, smem64);
    cudaFuncSetAttribute(fc_kernel, cudaFuncAttributeMaxDynamicSharedMemorySize, smemFc);

    const int warpBlocks = (NN * 32 + 255) / 256;

    convert_hist_kernel<<<(EE + MM + 255) / 256, 256>>>(edges, mask);
    scan1_kernel<<<NB1, 1024>>>();
    scan3_kernel<<<(NN + 255) / 256, 256>>>();
    mma_gemm_kernel<128><<<(NN + 63) / 64, 256, smem128>>>(x, W1, a_src1, a_dst1, g_hh_p, NN);
    scatter_kernel<<<(ETOT + 255) / 256, 256>>>(edges);
    agg_kernel<H1D><<<warpBlocks, 256>>>(g_hh_p, b1, g_out1_p);

    mma_gemm_kernel<64><<<(NN + 127) / 128, 256, smem64>>>(g_out1_p, W2, a_src2, a_dst2, g_hh_p, NN);
    agg_kernel<H2D><<<warpBlocks, 256>>>(g_hh_p, b2, g_out2_p);

    fc_kernel<<<MM / FCNPB, 256, smemFc>>>(g_out2_p, fc1_w, fc1_b, fc2_w, fc2_b, out);
}

// round 16
// speedup vs baseline: 1.1181x; 1.0057x over previous
#include <cuda_runtime.h>
#include <cuda_fp16.h>
#include <cstdint>

#define NN 100000
#define EE 1600000
#define ETOT (EE + NN)
#define FIN 128
#define H1D 128
#define H2D 64
#define FC1D 128
#define NCLS 10
#define MM 20000
#define SLOPE 0.2f
#define NB1 ((NN + 1023) / 1024)

// ---------------- scratch (device globals; no allocations allowed) ----------
__device__ int g_maskbuf[MM];
__device__ int g_cnt[NN];                       // zero-init; re-zeroed by scatter
__device__ int g_rank[EE];                      // per-edge arrival rank at its dst
__device__ int g_rowptr[NN + 1];
__device__ int g_col[ETOT];
__device__ int g_bsum[NB1];
__device__ __half g_hh[(size_t)NN * H1D];       // fp16 h (for gather)
__device__ float g_out1[(size_t)NN * H1D];
__device__ float g_out2[(size_t)NN * H2D];
__device__ float g_as[NN];
__device__ float g_ad[NN];

// ---------------- mma helpers (sm_80-portable HMMA path) ---------------------
__device__ __forceinline__ uint32_t smem_to_u32(const void* p) {
    uint32_t a;
    asm("{ .reg .u64 t; cvta.to.shared.u64 t, %1; cvt.u32.u64 %0, t; }" : "=r"(a) : "l"(p));
    return a;
}
__device__ __forceinline__ void ldsm_x4(uint32_t* r, uint32_t addr) {
    asm volatile("ldmatrix.sync.aligned.m8n8.x4.shared.b16 {%0,%1,%2,%3}, [%4];"
        : "=r"(r[0]), "=r"(r[1]), "=r"(r[2]), "=r"(r[3]) : "r"(addr));
}
__device__ __forceinline__ void ldsm_x4_t(uint32_t* r, uint32_t addr) {
    asm volatile("ldmatrix.sync.aligned.m8n8.x4.trans.shared.b16 {%0,%1,%2,%3}, [%4];"
        : "=r"(r[0]), "=r"(r[1]), "=r"(r[2]), "=r"(r[3]) : "r"(addr));
}
__device__ __forceinline__ void mma_f16(float* c, const uint32_t* a, uint32_t b0, uint32_t b1) {
    asm volatile(
        "mma.sync.aligned.m16n8k16.row.col.f32.f16.f16.f32 "
        "{%0,%1,%2,%3}, {%4,%5,%6,%7}, {%8,%9}, {%0,%1,%2,%3};"
        : "+f"(c[0]), "+f"(c[1]), "+f"(c[2]), "+f"(c[3])
        : "r"(a[0]), "r"(a[1]), "r"(a[2]), "r"(a[3]), "r"(b0), "r"(b1));
}
__device__ __forceinline__ uint32_t pack2h(float x, float y) {
    __half2 h = __floats2half2_rn(x, y);
    return *reinterpret_cast<uint32_t*>(&h);
}
__device__ __forceinline__ bool edges_is64(const void* edges) {
    const int* q = (const int*)edges;
    return (q[1] | q[3] | q[5] | q[7] | q[9] | q[11] | q[13] | q[15]) == 0;
}

// ---------------- CSR build ---------------------------------------------------
// histogram dst counts, record per-edge rank; convert mask
__global__ void convert_hist_kernel(const void* edges, const void* mask) {
    int i = blockIdx.x * blockDim.x + threadIdx.x;
    bool is64 = edges_is64(edges);
    if (i < EE) {
        int d = is64 ? (int)((const long long*)edges)[EE + i]
                     : ((const int*)edges)[EE + i];
        g_rank[i] = atomicAdd(&g_cnt[d], 1);
    } else if (i < EE + MM) {
        int j = i - EE;
        g_maskbuf[j] = is64 ? (int)((const long long*)mask)[j]
                            : ((const int*)mask)[j];
    }
}

__global__ void scan1_kernel() {
    __shared__ int sh[1024];
    int t = threadIdx.x;
    int gid = blockIdx.x * 1024 + t;
    int v = (gid < NN) ? (g_cnt[gid] + 1) : 0;   // +1 = self loop
    sh[t] = v;
    __syncthreads();
    for (int off = 1; off < 1024; off <<= 1) {
        int tv = (t >= off) ? sh[t - off] : 0;
        __syncthreads();
        sh[t] += tv;
        __syncthreads();
    }
    if (gid < NN) g_rowptr[gid] = sh[t] - v;
    if (t == 1023) g_bsum[blockIdx.x] = sh[1023];
}

__global__ void scan3_kernel() {
    __shared__ int sh[256];
    int t = threadIdx.x;
    int blk = (blockIdx.x * 256) >> 10;
    sh[t] = (t < blk) ? g_bsum[t] : 0;
    __syncthreads();
    for (int off = 128; off; off >>= 1) {
        if (t < off) sh[t] += sh[t + off];
        __syncthreads();
    }
    int offset = sh[0];
    int gid = blockIdx.x * 256 + t;
    if (gid < NN) g_rowptr[gid] += offset;
    if (gid == 0) g_rowptr[NN] = ETOT;
}

// scatter edges into CSR using precomputed ranks (NO atomics); re-zero g_cnt.
__global__ void scatter_kernel(const void* edges) {
    int i = blockIdx.x * blockDim.x + threadIdx.x;
    if (i >= ETOT) return;
    if (i < NN) g_cnt[i] = 0;                    // cleanup for next replay
    if (i < EE) {
        int s, d;
        if (edges_is64(edges)) {
            const long long* e = (const long long*)edges;
            s = (int)e[i];
            d = (int)e[EE + i];
        } else {
            const int* e = (const int*)edges;
            s = e[i];
            d = e[EE + i];
        }
        g_col[g_rowptr[d] + 1 + g_rank[i]] = s;
    } else {
        int n = i - EE;
        g_col[g_rowptr[n]] = n;                  // self loop
    }
}

// ---------------- HMMA fp16 single-stage full-K GEMM + fused alpha -----------
// A, B rounded once to fp16; full K=128 staged in ONE phase (single sync),
// then 8 uninterrupted k-steps. 256 threads / 8 warps, 2 CTAs/SM,
// CTA tile AROWS x NOUT, warp tile 16x64.
template <int NOUT>
__global__ __launch_bounds__(256, 2)
void mma_gemm_kernel(const float* __restrict__ A, const float* __restrict__ W,
                     const float* __restrict__ a_src, const float* __restrict__ a_dst,
                     __half* __restrict__ Ch, int nrows) {
    extern __shared__ char smem[];
    constexpr int AROWS = (NOUT == 128) ? 64 : 128;
    constexpr int ROWB = NOUT * 2;               // bytes per B smem k-row
    constexpr int OFF_A = 0;                     // AROWS x 128 fp16 (256B rows)
    constexpr int OFF_B = AROWS * 256;           // 128 k-rows x NOUT fp16
    constexpr int OFF_SA = OFF_B + 128 * ROWB;
    constexpr int OFF_SAL = OFF_SA + 2 * NOUT * 4;

    const int tid = threadIdx.x;
    const int wid = tid >> 5, lane = tid & 31;
    const int row0 = blockIdx.x * AROWS;
    const uint32_t sbase = smem_to_u32(smem);
    float* sa = (float*)(smem + OFF_SA);
    float* sd = sa + NOUT;
    float* sal = (float*)(smem + OFF_SAL);

    if (tid < NOUT) {
        sa[tid] = a_src[tid];
        sd[tid] = a_dst[tid];
    }
    if (tid < AROWS * 2) sal[tid] = 0.f;

    // ---- stage A [AROWS x 128] fp32 -> fp16, 256B rows, 16-chunk swizzle ----
    {
        constexpr int AITER = AROWS * 32 / 256;  // float4 groups / threads
#pragma unroll
        for (int it = 0; it < AITER; it++) {
            int idx4 = tid + it * 256;
            int r = idx4 >> 5;
            int k4 = (idx4 & 31) * 4;
            int gr = row0 + r;
            float4 v = (gr < nrows) ? *(const float4*)&A[(size_t)gr * 128 + k4]
                                    : make_float4(0.f, 0.f, 0.f, 0.f);
            uint2 uh = make_uint2(pack2h(v.x, v.y), pack2h(v.z, v.w));
            uint32_t off = (uint32_t)r * 256
                         + ((((k4 >> 3) ^ (r & 7)) & 15) << 4) + (k4 & 7) * 2;
            *(uint2*)(smem + OFF_A + off) = uh;
        }
    }
    // ---- stage B [128 x NOUT] fp32 -> fp16 ----
    {
        constexpr int QPR = NOUT / 4;
        constexpr int BITER = 128 * QPR / 256;
#pragma unroll
        for (int it = 0; it < BITER; it++) {
            int idx = tid + it * 256;
            int kk = idx / QPR;
            int n4 = (idx % QPR) * 4;
            float4 v = *(const float4*)&W[(size_t)kk * NOUT + n4];
            uint2 uh = make_uint2(pack2h(v.x, v.y), pack2h(v.z, v.w));
            uint32_t off = (uint32_t)kk * ROWB + ((((n4 >> 3) ^ (kk & 7)) << 4) + (n4 & 7) * 2);
            *(uint2*)(smem + OFF_B + off) = uh;
        }
    }
    __syncthreads();

    // warp tiling: 16x64 warp tiles
    const int m0w = (NOUT == 128) ? (wid >> 1) * 16 : wid * 16;
    const int wn  = (NOUT == 128) ? (wid & 1) * 64 : 0;

    float acc[8][4];
#pragma unroll
    for (int nt = 0; nt < 8; nt++)
#pragma unroll
        for (int q = 0; q < 4; q++) acc[nt][q] = 0.f;

    const int a_row = lane & 15;
    const int a_cadd = lane >> 4;
    const int b_row = lane & 15;
    const int b_cadd = lane >> 4;

    // ---- 8 uninterrupted k-steps of 16 ----
#pragma unroll
    for (int ks = 0; ks < 8; ks++) {
        uint32_t ah[4];
        {
            int r = m0w + a_row;
            int chunk = ks * 2 + a_cadd;
            uint32_t off = (uint32_t)r * 256 + (((chunk ^ (r & 7)) & 15) << 4);
            ldsm_x4(ah, sbase + OFF_A + off);
        }
#pragma unroll
        for (int p = 0; p < 4; p++) {
            int nbase = wn + p * 16;
            int r = ks * 16 + b_row;
            int chunkb = (nbase >> 3) + b_cadd;
            uint32_t off = (uint32_t)r * ROWB + (((chunkb ^ (r & 7)) & (ROWB / 16 - 1)) << 4);
            uint32_t bf[4];
            ldsm_x4_t(bf, sbase + OFF_B + off);
            mma_f16(acc[2 * p],     ah, bf[0], bf[1]);
            mma_f16(acc[2 * p + 1], ah, bf[2], bf[3]);
        }
    }

    // ---- epilogue: fp16 store + fused alpha reduction ----
    const int group = lane >> 2;
    const int tc = (lane & 3) * 2;
    {
        int r0 = row0 + m0w + group;
        int r1 = r0 + 8;
        float s0 = 0.f, d0 = 0.f, s1 = 0.f, d1 = 0.f;
#pragma unroll
        for (int nt = 0; nt < 8; nt++) {
            int col = wn + nt * 8 + tc;
            float va0 = sa[col], va1 = sa[col + 1];
            float vd0 = sd[col], vd1 = sd[col + 1];
            s0 += acc[nt][0] * va0 + acc[nt][1] * va1;
            d0 += acc[nt][0] * vd0 + acc[nt][1] * vd1;
            s1 += acc[nt][2] * va0 + acc[nt][3] * va1;
            d1 += acc[nt][2] * vd0 + acc[nt][3] * vd1;
            if (r0 < nrows)
                *(__half2*)&Ch[(size_t)r0 * NOUT + col] = __floats2half2_rn(acc[nt][0], acc[nt][1]);
            if (r1 < nrows)
                *(__half2*)&Ch[(size_t)r1 * NOUT + col] = __floats2half2_rn(acc[nt][2], acc[nt][3]);
        }
#pragma unroll
        for (int m = 1; m <= 2; m <<= 1) {
            s0 += __shfl_xor_sync(0xffffffffu, s0, m);
            d0 += __shfl_xor_sync(0xffffffffu, d0, m);
            s1 += __shfl_xor_sync(0xffffffffu, s1, m);
            d1 += __shfl_xor_sync(0xffffffffu, d1, m);
        }
        if ((lane & 3) == 0) {
            int rl = m0w + group;
            atomicAdd(&sal[rl * 2], s0);
            atomicAdd(&sal[rl * 2 + 1], d0);
            atomicAdd(&sal[(rl + 8) * 2], s1);
            atomicAdd(&sal[(rl + 8) * 2 + 1], d1);
        }
    }
    __syncthreads();
    if (tid < AROWS) {
        int row = row0 + tid;
        if (row < nrows) {
            g_as[row] = sal[tid * 2];
            g_ad[row] = sal[tid * 2 + 1];
        }
    }
}

// ---------------- fused softmax + gather: warp per node, fp16 h, 4-unroll ----
template <int F>
__global__ void agg_kernel(const __half* __restrict__ hh, const float* __restrict__ bias,
                           float* __restrict__ out) {
    constexpr int V = F / 32;
    int node = (blockIdx.x * blockDim.x + threadIdx.x) >> 5;
    int lane = threadIdx.x & 31;
    if (node >= NN) return;
    int idx = g_rowptr[node];
    const int end = g_rowptr[node + 1];
    const float adv = g_ad[node];
    float mm = g_as[node] + adv;
    const float m = (mm > 0.f) ? mm : SLOPE * mm;
    float Z = 0.f;
    float acc[V];
#pragma unroll
    for (int j = 0; j < V; j++) acc[j] = 0.f;

    for (; idx + 4 <= end; idx += 4) {
        int s0 = g_col[idx];
        int s1 = g_col[idx + 1];
        int s2 = g_col[idx + 2];
        int s3 = g_col[idx + 3];
        float e0 = g_as[s0] + adv;
        float e1 = g_as[s1] + adv;
        float e2 = g_as[s2] + adv;
        float e3 = g_as[s3] + adv;
        e0 = (e0 > 0.f) ? e0 : SLOPE * e0;
        e1 = (e1 > 0.f) ? e1 : SLOPE * e1;
        e2 = (e2 > 0.f) ? e2 : SLOPE * e2;
        e3 = (e3 > 0.f) ? e3 : SLOPE * e3;
        float w0 = __expf(e0 - m);
        float w1 = __expf(e1 - m);
        float w2 = __expf(e2 - m);
        float w3 = __expf(e3 - m);
        Z += (w0 + w1) + (w2 + w3);
        if (V == 4) {
            uint2 u0 = *(const uint2*)&hh[(size_t)s0 * F + lane * 4];
            uint2 u1 = *(const uint2*)&hh[(size_t)s1 * F + lane * 4];
            uint2 u2 = *(const uint2*)&hh[(size_t)s2 * F + lane * 4];
            uint2 u3 = *(const uint2*)&hh[(size_t)s3 * F + lane * 4];
            float2 a0 = __half22float2(*(const __half2*)&u0.x);
            float2 b0 = __half22float2(*(const __half2*)&u0.y);
            float2 a1 = __half22float2(*(const __half2*)&u1.x);
            float2 b1 = __half22float2(*(const __half2*)&u1.y);
            float2 a2 = __half22float2(*(const __half2*)&u2.x);
            float2 b2 = __half22float2(*(const __half2*)&u2.y);
            float2 a3 = __half22float2(*(const __half2*)&u3.x);
            float2 b3 = __half22float2(*(const __half2*)&u3.y);
            acc[0] += (w0 * a0.x + w1 * a1.x) + (w2 * a2.x + w3 * a3.x);
            acc[1] += (w0 * a0.y + w1 * a1.y) + (w2 * a2.y + w3 * a3.y);
            acc[2] += (w0 * b0.x + w1 * b1.x) + (w2 * b2.x + w3 * b3.x);
            acc[3] += (w0 * b0.y + w1 * b1.y) + (w2 * b2.y + w3 * b3.y);
        } else {
            float2 a0 = __half22float2(*(const __half2*)&hh[(size_t)s0 * F + lane * 2]);
            float2 a1 = __half22float2(*(const __half2*)&hh[(size_t)s1 * F + lane * 2]);
            float2 a2 = __half22float2(*(const __half2*)&hh[(size_t)s2 * F + lane * 2]);
            float2 a3 = __half22float2(*(const __half2*)&hh[(size_t)s3 * F + lane * 2]);
            acc[0] += (w0 * a0.x + w1 * a1.x) + (w2 * a2.x + w3 * a3.x);
            acc[1] += (w0 * a0.y + w1 * a1.y) + (w2 * a2.y + w3 * a3.y);
        }
    }
    for (; idx < end; idx++) {
        int s0 = g_col[idx];
        float e0 = g_as[s0] + adv;
        e0 = (e0 > 0.f) ? e0 : SLOPE * e0;
        float w0 = __expf(e0 - m);
        Z += w0;
        if (V == 4) {
            uint2 u0 = *(const uint2*)&hh[(size_t)s0 * F + lane * 4];
            float2 a0 = __half22float2(*(const __half2*)&u0.x);
            float2 b0 = __half22float2(*(const __half2*)&u0.y);
            acc[0] += w0 * a0.x; acc[1] += w0 * a0.y;
            acc[2] += w0 * b0.x; acc[3] += w0 * b0.y;
        } else {
            float2 a0 = __half22float2(*(const __half2*)&hh[(size_t)s0 * F + lane * 2]);
            acc[0] += w0 * a0.x; acc[1] += w0 * a0.y;
        }
    }

    const float iz = 1.f / Z;
    if (V == 4) {
        float4 b4 = *(const float4*)&bias[lane * 4];
        float4 o;
        o.x = fmaxf(acc[0] * iz + b4.x, 0.f);
        o.y = fmaxf(acc[1] * iz + b4.y, 0.f);
        o.z = fmaxf(acc[2] * iz + b4.z, 0.f);
        o.w = fmaxf(acc[3] * iz + b4.w, 0.f);
        *(float4*)&out[(size_t)node * F + lane * 4] = o;
    } else {
        float2 b2 = *(const float2*)&bias[lane * 2];
        float2 o;
        o.x = fmaxf(acc[0] * iz + b2.x, 0.f);
        o.y = fmaxf(acc[1] * iz + b2.y, 0.f);
        *(float2*)&out[(size_t)node * F + lane * 2] = o;
    }
}

// ---------------- FC head: 32 mask-nodes per block, weights staged in smem ---
#define FCNPB 32
__global__ __launch_bounds__(256)
void fc_kernel(const float* __restrict__ feat,
               const float* __restrict__ w1, const float* __restrict__ b1,
               const float* __restrict__ w2, const float* __restrict__ b2,
               float* __restrict__ out) {
    extern __shared__ float sm[];
    float* sw1 = sm;
    float* sw2 = sw1 + 64 * 128;
    float* sf  = sw2 + 128 * 12;
    float* sz  = sf + FCNPB * 64;

    const int tid = threadIdx.x;
    const int mi0 = blockIdx.x * FCNPB;

#pragma unroll
    for (int it = 0; it < 8; it++) {
        int i4 = tid + it * 256;
        *(float4*)&sw1[i4 * 4] = *(const float4*)&w1[i4 * 4];
    }
    for (int i = tid; i < 128 * NCLS; i += 256)
        sw2[(i / NCLS) * 12 + (i % NCLS)] = w2[i];
#pragma unroll
    for (int it = 0; it < 2; it++) {
        int i4 = tid + it * 256;
        int n = i4 >> 4;
        int c4 = (i4 & 15) * 4;
        int node = g_maskbuf[mi0 + n];
        *(float4*)&sf[n * 64 + c4] = *(const float4*)&feat[(size_t)node * H2D + c4];
    }
    __syncthreads();

#pragma unroll
    for (int it = 0; it < 16; it++) {
        int oi = tid + it * 256;
        int n = oi >> 7;
        int t = oi & 127;
        float acc = b1[t];
#pragma unroll
        for (int k = 0; k < 64; k++)
            acc += sf[n * 64 + k] * sw1[k * 128 + t];
        sz[n * 128 + t] = fmaxf(acc, 0.f);
    }
    __syncthreads();

    for (int oi = tid; oi < FCNPB * NCLS; oi += 256) {
        int n = oi / NCLS;
        int c = oi % NCLS;
        float acc = b2[c];
#pragma unroll
        for (int j = 0; j < 128; j++)
            acc += sz[n * 128 + j] * sw2[j * 12 + c];
        out[(size_t)(mi0 + n) * NCLS + c] = acc;
    }
}

// ---------------- launch -----------------------------------------------------
extern "C" void kernel_launch(void* const* d_in, const int* in_sizes, int n_in,
                              void* d_out, int out_size) {
    const float* x      = (const float*)d_in[0];
    const void*  edges  = d_in[1];
    const void*  mask   = d_in[2];
    const float* W1     = (const float*)d_in[3];
    const float* a_src1 = (const float*)d_in[4];
    const float* a_dst1 = (const float*)d_in[5];
    const float* b1     = (const float*)d_in[6];
    const float* W2     = (const float*)d_in[7];
    const float* a_src2 = (const float*)d_in[8];
    const float* a_dst2 = (const float*)d_in[9];
    const float* b2     = (const float*)d_in[10];
    const float* fc1_w  = (const float*)d_in[11];
    const float* fc1_b  = (const float*)d_in[12];
    const float* fc2_w  = (const float*)d_in[13];
    const float* fc2_b  = (const float*)d_in[14];
    float* out = (float*)d_out;

    __half* g_hh_p;   cudaGetSymbolAddress((void**)&g_hh_p, g_hh);
    float* g_out1_p;  cudaGetSymbolAddress((void**)&g_out1_p, g_out1);
    float* g_out2_p;  cudaGetSymbolAddress((void**)&g_out2_p, g_out2);

    // smem: A AROWS*256 + B 128*ROWB + sa/sd + sal
    const int smem128 = 64 * 256 + 128 * 256 + 2 * 128 * 4 + 64 * 2 * 4;       // 50688
    const int smem64  = 128 * 256 + 128 * 128 + 2 * 64 * 4 + 128 * 2 * 4;      // 50688
    const int smemFc  = (64 * 128 + 128 * 12 + FCNPB * 64 + FCNPB * 128) * 4;  // 63488
    cudaFuncSetAttribute(mma_gemm_kernel<128>, cudaFuncAttributeMaxDynamicSharedMemorySize, smem128);
    cudaFuncSetAttribute(mma_gemm_kernel<64>,  cudaFuncAttributeMaxDynamicSharedMemorySize, smem64);
    cudaFuncSetAttribute(fc_kernel, cudaFuncAttributeMaxDynamicSharedMemorySize, smemFc);

    const int warpBlocks = (NN * 32 + 255) / 256;

    convert_hist_kernel<<<(EE + MM + 255) / 256, 256>>>(edges, mask);
    scan1_kernel<<<NB1, 1024>>>();
    scan3_kernel<<<(NN + 255) / 256, 256>>>();
    mma_gemm_kernel<128><<<(NN + 63) / 64, 256, smem128>>>(x, W1, a_src1, a_dst1, g_hh_p, NN);
    scatter_kernel<<<(ETOT + 255) / 256, 256>>>(edges);
    agg_kernel<H1D><<<warpBlocks, 256>>>(g_hh_p, b1, g_out1_p);

    mma_gemm_kernel<64><<<(NN + 127) / 128, 256, smem64>>>(g_out1_p, W2, a_src2, a_dst2, g_hh_p, NN);
    agg_kernel<H2D><<<warpBlocks, 256>>>(g_hh_p, b2, g_out2_p);

    fc_kernel<<<MM / FCNPB, 256, smemFc>>>(g_out2_p, fc1_w, fc1_b, fc2_w, fc2_b, out);
}

// round 17
// speedup vs baseline: 1.1392x; 1.0189x over previous
#include <cuda_runtime.h>
#include <cuda_fp16.h>
#include <cstdint>

#define NN 100000
#define EE 1600000
#define ETOT (EE + NN)
#define FIN 128
#define H1D 128
#define H2D 64
#define FC1D 128
#define NCLS 10
#define MM 20000
#define SLOPE 0.2f
#define NB1 ((NN + 1023) / 1024)
#define W1ELEM (FIN * H1D)        // 16384
#define W2ELEM (H1D * H2D)        // 8192
#define WCONV4 ((W1ELEM + W2ELEM) / 4)  // 6144 float4 groups

// ---------------- scratch (device globals; no allocations allowed) ----------
__device__ int g_maskbuf[MM];
__device__ int g_cnt[NN];                       // zero-init; re-zeroed by scatter
__device__ int g_rank[EE];                      // per-edge arrival rank at its dst
__device__ int g_rowptr[NN + 1];
__device__ int g_col[ETOT];
__device__ int g_bsum[NB1];
__device__ __half g_w1h[W1ELEM];                // fp16 W1 (pre-converted)
__device__ __half g_w2h[W2ELEM];                // fp16 W2 (pre-converted)
__device__ __half g_hh[(size_t)NN * H1D];       // fp16 h (for gather)
__device__ float g_out1[(size_t)NN * H1D];
__device__ float g_out2[(size_t)NN * H2D];
__device__ float g_as[NN];
__device__ float g_ad[NN];

// ---------------- mma helpers (sm_80-portable HMMA path) ---------------------
__device__ __forceinline__ uint32_t smem_to_u32(const void* p) {
    uint32_t a;
    asm("{ .reg .u64 t; cvta.to.shared.u64 t, %1; cvt.u32.u64 %0, t; }" : "=r"(a) : "l"(p));
    return a;
}
__device__ __forceinline__ void ldsm_x4(uint32_t* r, uint32_t addr) {
    asm volatile("ldmatrix.sync.aligned.m8n8.x4.shared.b16 {%0,%1,%2,%3}, [%4];"
        : "=r"(r[0]), "=r"(r[1]), "=r"(r[2]), "=r"(r[3]) : "r"(addr));
}
__device__ __forceinline__ void ldsm_x4_t(uint32_t* r, uint32_t addr) {
    asm volatile("ldmatrix.sync.aligned.m8n8.x4.trans.shared.b16 {%0,%1,%2,%3}, [%4];"
        : "=r"(r[0]), "=r"(r[1]), "=r"(r[2]), "=r"(r[3]) : "r"(addr));
}
__device__ __forceinline__ void mma_f16(float* c, const uint32_t* a, uint32_t b0, uint32_t b1) {
    asm volatile(
        "mma.sync.aligned.m16n8k16.row.col.f32.f16.f16.f32 "
        "{%0,%1,%2,%3}, {%4,%5,%6,%7}, {%8,%9}, {%0,%1,%2,%3};"
        : "+f"(c[0]), "+f"(c[1]), "+f"(c[2]), "+f"(c[3])
        : "r"(a[0]), "r"(a[1]), "r"(a[2]), "r"(a[3]), "r"(b0), "r"(b1));
}
__device__ __forceinline__ uint32_t pack2h(float x, float y) {
    __half2 h = __floats2half2_rn(x, y);
    return *reinterpret_cast<uint32_t*>(&h);
}
__device__ __forceinline__ bool edges_is64(const void* edges) {
    const int* q = (const int*)edges;
    return (q[1] | q[3] | q[5] | q[7] | q[9] | q[11] | q[13] | q[15]) == 0;
}

// ---------------- CSR build + W fp16 pre-conversion ---------------------------
__global__ void convert_hist_kernel(const void* edges, const void* mask,
                                    const float* __restrict__ W1,
                                    const float* __restrict__ W2) {
    int i = blockIdx.x * blockDim.x + threadIdx.x;
    bool is64 = edges_is64(edges);
    if (i < EE) {
        int d = is64 ? (int)((const long long*)edges)[EE + i]
                     : ((const int*)edges)[EE + i];
        g_rank[i] = atomicAdd(&g_cnt[d], 1);
    } else if (i < EE + MM) {
        int j = i - EE;
        g_maskbuf[j] = is64 ? (int)((const long long*)mask)[j]
                            : ((const int*)mask)[j];
    } else if (i < EE + MM + WCONV4) {
        int j = i - (EE + MM);
        if (j < W1ELEM / 4) {
            float4 v = *(const float4*)&W1[j * 4];
            *(uint2*)&g_w1h[j * 4] = make_uint2(pack2h(v.x, v.y), pack2h(v.z, v.w));
        } else {
            int j2 = j - W1ELEM / 4;
            float4 v = *(const float4*)&W2[j2 * 4];
            *(uint2*)&g_w2h[j2 * 4] = make_uint2(pack2h(v.x, v.y), pack2h(v.z, v.w));
        }
    }
}

__global__ void scan1_kernel() {
    __shared__ int sh[1024];
    int t = threadIdx.x;
    int gid = blockIdx.x * 1024 + t;
    int v = (gid < NN) ? (g_cnt[gid] + 1) : 0;   // +1 = self loop
    sh[t] = v;
    __syncthreads();
    for (int off = 1; off < 1024; off <<= 1) {
        int tv = (t >= off) ? sh[t - off] : 0;
        __syncthreads();
        sh[t] += tv;
        __syncthreads();
    }
    if (gid < NN) g_rowptr[gid] = sh[t] - v;
    if (t == 1023) g_bsum[blockIdx.x] = sh[1023];
}

__global__ void scan3_kernel() {
    __shared__ int sh[256];
    int t = threadIdx.x;
    int blk = (blockIdx.x * 256) >> 10;
    sh[t] = (t < blk) ? g_bsum[t] : 0;
    __syncthreads();
    for (int off = 128; off; off >>= 1) {
        if (t < off) sh[t] += sh[t + off];
        __syncthreads();
    }
    int offset = sh[0];
    int gid = blockIdx.x * 256 + t;
    if (gid < NN) g_rowptr[gid] += offset;
    if (gid == 0) g_rowptr[NN] = ETOT;
}

// scatter edges into CSR using precomputed ranks (NO atomics); re-zero g_cnt.
__global__ void scatter_kernel(const void* edges) {
    int i = blockIdx.x * blockDim.x + threadIdx.x;
    if (i >= ETOT) return;
    if (i < NN) g_cnt[i] = 0;                    // cleanup for next replay
    if (i < EE) {
        int s, d;
        if (edges_is64(edges)) {
            const long long* e = (const long long*)edges;
            s = (int)e[i];
            d = (int)e[EE + i];
        } else {
            const int* e = (const int*)edges;
            s = e[i];
            d = e[EE + i];
        }
        g_col[g_rowptr[d] + 1 + g_rank[i]] = s;
    } else {
        int n = i - EE;
        g_col[g_rowptr[n]] = n;                  // self loop
    }
}

// ---------------- HMMA fp16 single-stage GEMM + fused alpha ------------------
// A rounded to fp16 in staging; B pre-converted (g_w*h) -> pure swizzled copy.
// 256 threads / 8 warps, 2 CTAs/SM, CTA tile 128 x NOUT.
// NOUT=128: 4 m-groups x 2 n-groups, MI=2 (warp tile 32x64) -> 6 ldsm / 16 mma.
// NOUT=64 : 8 m-groups, MI=1 (warp tile 16x64).
template <int NOUT>
__global__ __launch_bounds__(256, 2)
void mma_gemm_kernel(const float* __restrict__ A, const __half* __restrict__ Wh,
                     const float* __restrict__ a_src, const float* __restrict__ a_dst,
                     __half* __restrict__ Ch, int nrows) {
    extern __shared__ char smem[];
    constexpr int AROWS = 128;
    constexpr int ROWB = NOUT * 2;               // bytes per B smem k-row
    constexpr int CPR = ROWB / 16;               // 16B chunks per B row
    constexpr int MI = (NOUT == 128) ? 2 : 1;
    constexpr int OFF_A = 0;                     // 128 x 128 fp16 (256B rows)
    constexpr int OFF_B = AROWS * 256;           // 128 k-rows x NOUT fp16
    constexpr int OFF_SA = OFF_B + 128 * ROWB;
    constexpr int OFF_SAL = OFF_SA + 2 * NOUT * 4;

    const int tid = threadIdx.x;
    const int wid = tid >> 5, lane = tid & 31;
    const int row0 = blockIdx.x * AROWS;
    const uint32_t sbase = smem_to_u32(smem);
    float* sa = (float*)(smem + OFF_SA);
    float* sd = sa + NOUT;
    float* sal = (float*)(smem + OFF_SAL);

    if (tid < NOUT) {
        sa[tid] = a_src[tid];
        sd[tid] = a_dst[tid];
    }
    sal[tid] = 0.f;                              // 128 rows x {s,d} = 256

    // ---- stage A [128 x 128] fp32 -> fp16, 256B rows, 16-chunk swizzle ----
#pragma unroll
    for (int it = 0; it < 16; it++) {
        int idx4 = tid + it * 256;
        int r = idx4 >> 5;
        int k4 = (idx4 & 31) * 4;
        int gr = row0 + r;
        float4 v = (gr < nrows) ? *(const float4*)&A[(size_t)gr * 128 + k4]
                                : make_float4(0.f, 0.f, 0.f, 0.f);
        uint2 uh = make_uint2(pack2h(v.x, v.y), pack2h(v.z, v.w));
        uint32_t off = (uint32_t)r * 256
                     + ((((k4 >> 3) ^ (r & 7)) & 15) << 4) + (k4 & 7) * 2;
        *(uint2*)(smem + OFF_A + off) = uh;
    }
    // ---- stage B [128 x NOUT] fp16 -> fp16 swizzled copy (uint4) ----
    {
        constexpr int BITER = 128 * CPR / 256;
#pragma unroll
        for (int it = 0; it < BITER; it++) {
            int idx = tid + it * 256;
            int kk = idx / CPR;
            int cx = idx % CPR;
            uint4 v = *(const uint4*)&Wh[(size_t)kk * NOUT + cx * 8];
            uint32_t off = (uint32_t)kk * ROWB + (((cx ^ (kk & 7)) & (CPR - 1)) << 4);
            *(uint4*)(smem + OFF_B + off) = v;
        }
    }
    __syncthreads();

    // warp tiling
    const int m0w = (NOUT == 128) ? (wid >> 1) * 32 : wid * 16;
    const int wn  = (NOUT == 128) ? (wid & 1) * 64 : 0;

    float acc[MI][8][4];
#pragma unroll
    for (int mi = 0; mi < MI; mi++)
#pragma unroll
        for (int nt = 0; nt < 8; nt++)
#pragma unroll
            for (int q = 0; q < 4; q++) acc[mi][nt][q] = 0.f;

    const int a_row = lane & 15;
    const int a_cadd = lane >> 4;
    const int b_row = lane & 15;
    const int b_cadd = lane >> 4;

    // ---- 8 uninterrupted k-steps of 16 ----
#pragma unroll
    for (int ks = 0; ks < 8; ks++) {
        uint32_t ah[MI][4];
#pragma unroll
        for (int mi = 0; mi < MI; mi++) {
            int r = m0w + mi * 16 + a_row;
            int chunk = ks * 2 + a_cadd;
            uint32_t off = (uint32_t)r * 256 + (((chunk ^ (r & 7)) & 15) << 4);
            ldsm_x4(ah[mi], sbase + OFF_A + off);
        }
#pragma unroll
        for (int p = 0; p < 4; p++) {
            int nbase = wn + p * 16;
            int r = ks * 16 + b_row;
            int chunkb = (nbase >> 3) + b_cadd;
            uint32_t off = (uint32_t)r * ROWB + (((chunkb ^ (r & 7)) & (CPR - 1)) << 4);
            uint32_t bf[4];
            ldsm_x4_t(bf, sbase + OFF_B + off);
#pragma unroll
            for (int mi = 0; mi < MI; mi++) {
                mma_f16(acc[mi][2 * p],     ah[mi], bf[0], bf[1]);
                mma_f16(acc[mi][2 * p + 1], ah[mi], bf[2], bf[3]);
            }
        }
    }

    // ---- epilogue: fp16 store + fused alpha reduction ----
    const int group = lane >> 2;
    const int tc = (lane & 3) * 2;
#pragma unroll
    for (int mi = 0; mi < MI; mi++) {
        int r0 = row0 + m0w + mi * 16 + group;
        int r1 = r0 + 8;
        float s0 = 0.f, d0 = 0.f, s1 = 0.f, d1 = 0.f;
#pragma unroll
        for (int nt = 0; nt < 8; nt++) {
            int col = wn + nt * 8 + tc;
            float va0 = sa[col], va1 = sa[col + 1];
            float vd0 = sd[col], vd1 = sd[col + 1];
            s0 += acc[mi][nt][0] * va0 + acc[mi][nt][1] * va1;
            d0 += acc[mi][nt][0] * vd0 + acc[mi][nt][1] * vd1;
            s1 += acc[mi][nt][2] * va0 + acc[mi][nt][3] * va1;
            d1 += acc[mi][nt][2] * vd0 + acc[mi][nt][3] * vd1;
            if (r0 < nrows)
                *(__half2*)&Ch[(size_t)r0 * NOUT + col] = __floats2half2_rn(acc[mi][nt][0], acc[mi][nt][1]);
            if (r1 < nrows)
                *(__half2*)&Ch[(size_t)r1 * NOUT + col] = __floats2half2_rn(acc[mi][nt][2], acc[mi][nt][3]);
        }
#pragma unroll
        for (int m = 1; m <= 2; m <<= 1) {
            s0 += __shfl_xor_sync(0xffffffffu, s0, m);
            d0 += __shfl_xor_sync(0xffffffffu, d0, m);
            s1 += __shfl_xor_sync(0xffffffffu, s1, m);
            d1 += __shfl_xor_sync(0xffffffffu, d1, m);
        }
        if ((lane & 3) == 0) {
            int rl = m0w + mi * 16 + group;
            atomicAdd(&sal[rl * 2], s0);
            atomicAdd(&sal[rl * 2 + 1], d0);
            atomicAdd(&sal[(rl + 8) * 2], s1);
            atomicAdd(&sal[(rl + 8) * 2 + 1], d1);
        }
    }
    __syncthreads();
    if (tid < AROWS) {
        int row = row0 + tid;
        if (row < nrows) {
            g_as[row] = sal[tid * 2];
            g_ad[row] = sal[tid * 2 + 1];
        }
    }
}

// ---------------- fused softmax + gather: warp per node, fp16 h, 4-unroll ----
template <int F>
__global__ void agg_kernel(const __half* __restrict__ hh, const float* __restrict__ bias,
                           float* __restrict__ out) {
    constexpr int V = F / 32;
    int node = (blockIdx.x * blockDim.x + threadIdx.x) >> 5;
    int lane = threadIdx.x & 31;
    if (node >= NN) return;
    int idx = g_rowptr[node];
    const int end = g_rowptr[node + 1];
    const float adv = g_ad[node];
    float mm = g_as[node] + adv;
    const float m = (mm > 0.f) ? mm : SLOPE * mm;
    float Z = 0.f;
    float acc[V];
#pragma unroll
    for (int j = 0; j < V; j++) acc[j] = 0.f;

    for (; idx + 4 <= end; idx += 4) {
        int s0 = g_col[idx];
        int s1 = g_col[idx + 1];
        int s2 = g_col[idx + 2];
        int s3 = g_col[idx + 3];
        float e0 = g_as[s0] + adv;
        float e1 = g_as[s1] + adv;
        float e2 = g_as[s2] + adv;
        float e3 = g_as[s3] + adv;
        e0 = (e0 > 0.f) ? e0 : SLOPE * e0;
        e1 = (e1 > 0.f) ? e1 : SLOPE * e1;
        e2 = (e2 > 0.f) ? e2 : SLOPE * e2;
        e3 = (e3 > 0.f) ? e3 : SLOPE * e3;
        float w0 = __expf(e0 - m);
        float w1 = __expf(e1 - m);
        float w2 = __expf(e2 - m);
        float w3 = __expf(e3 - m);
        Z += (w0 + w1) + (w2 + w3);
        if (V == 4) {
            uint2 u0 = *(const uint2*)&hh[(size_t)s0 * F + lane * 4];
            uint2 u1 = *(const uint2*)&hh[(size_t)s1 * F + lane * 4];
            uint2 u2 = *(const uint2*)&hh[(size_t)s2 * F + lane * 4];
            uint2 u3 = *(const uint2*)&hh[(size_t)s3 * F + lane * 4];
            float2 a0 = __half22float2(*(const __half2*)&u0.x);
            float2 b0 = __half22float2(*(const __half2*)&u0.y);
            float2 a1 = __half22float2(*(const __half2*)&u1.x);
            float2 b1 = __half22float2(*(const __half2*)&u1.y);
            float2 a2 = __half22float2(*(const __half2*)&u2.x);
            float2 b2 = __half22float2(*(const __half2*)&u2.y);
            float2 a3 = __half22float2(*(const __half2*)&u3.x);
            float2 b3 = __half22float2(*(const __half2*)&u3.y);
            acc[0] += (w0 * a0.x + w1 * a1.x) + (w2 * a2.x + w3 * a3.x);
            acc[1] += (w0 * a0.y + w1 * a1.y) + (w2 * a2.y + w3 * a3.y);
            acc[2] += (w0 * b0.x + w1 * b1.x) + (w2 * b2.x + w3 * b3.x);
            acc[3] += (w0 * b0.y + w1 * b1.y) + (w2 * b2.y + w3 * b3.y);
        } else {
            float2 a0 = __half22float2(*(const __half2*)&hh[(size_t)s0 * F + lane * 2]);
            float2 a1 = __half22float2(*(const __half2*)&hh[(size_t)s1 * F + lane * 2]);
            float2 a2 = __half22float2(*(const __half2*)&hh[(size_t)s2 * F + lane * 2]);
            float2 a3 = __half22float2(*(const __half2*)&hh[(size_t)s3 * F + lane * 2]);
            acc[0] += (w0 * a0.x + w1 * a1.x) + (w2 * a2.x + w3 * a3.x);
            acc[1] += (w0 * a0.y + w1 * a1.y) + (w2 * a2.y + w3 * a3.y);
        }
    }
    for (; idx < end; idx++) {
        int s0 = g_col[idx];
        float e0 = g_as[s0] + adv;
        e0 = (e0 > 0.f) ? e0 : SLOPE * e0;
        float w0 = __expf(e0 - m);
        Z += w0;
        if (V == 4) {
            uint2 u0 = *(const uint2*)&hh[(size_t)s0 * F + lane * 4];
            float2 a0 = __half22float2(*(const __half2*)&u0.x);
            float2 b0 = __half22float2(*(const __half2*)&u0.y);
            acc[0] += w0 * a0.x; acc[1] += w0 * a0.y;
            acc[2] += w0 * b0.x; acc[3] += w0 * b0.y;
        } else {
            float2 a0 = __half22float2(*(const __half2*)&hh[(size_t)s0 * F + lane * 2]);
            acc[0] += w0 * a0.x; acc[1] += w0 * a0.y;
        }
    }

    const float iz = 1.f / Z;
    if (V == 4) {
        float4 b4 = *(const float4*)&bias[lane * 4];
        float4 o;
        o.x = fmaxf(acc[0] * iz + b4.x, 0.f);
        o.y = fmaxf(acc[1] * iz + b4.y, 0.f);
        o.z = fmaxf(acc[2] * iz + b4.z, 0.f);
        o.w = fmaxf(acc[3] * iz + b4.w, 0.f);
        *(float4*)&out[(size_t)node * F + lane * 4] = o;
    } else {
        float2 b2 = *(const float2*)&bias[lane * 2];
        float2 o;
        o.x = fmaxf(acc[0] * iz + b2.x, 0.f);
        o.y = fmaxf(acc[1] * iz + b2.y, 0.f);
        *(float2*)&out[(size_t)node * F + lane * 2] = o;
    }
}

// ---------------- FC head: 32 mask-nodes per block, weights staged in smem ---
#define FCNPB 32
__global__ __launch_bounds__(256)
void fc_kernel(const float* __restrict__ feat,
               const float* __restrict__ w1, const float* __restrict__ b1,
               const float* __restrict__ w2, const float* __restrict__ b2,
               float* __restrict__ out) {
    extern __shared__ float sm[];
    float* sw1 = sm;
    float* sw2 = sw1 + 64 * 128;
    float* sf  = sw2 + 128 * 12;
    float* sz  = sf + FCNPB * 64;

    const int tid = threadIdx.x;
    const int mi0 = blockIdx.x * FCNPB;

#pragma unroll
    for (int it = 0; it < 8; it++) {
        int i4 = tid + it * 256;
        *(float4*)&sw1[i4 * 4] = *(const float4*)&w1[i4 * 4];
    }
    for (int i = tid; i < 128 * NCLS; i += 256)
        sw2[(i / NCLS) * 12 + (i % NCLS)] = w2[i];
#pragma unroll
    for (int it = 0; it < 2; it++) {
        int i4 = tid + it * 256;
        int n = i4 >> 4;
        int c4 = (i4 & 15) * 4;
        int node = g_maskbuf[mi0 + n];
        *(float4*)&sf[n * 64 + c4] = *(const float4*)&feat[(size_t)node * H2D + c4];
    }
    __syncthreads();

#pragma unroll
    for (int it = 0; it < 16; it++) {
        int oi = tid + it * 256;
        int n = oi >> 7;
        int t = oi & 127;
        float acc = b1[t];
#pragma unroll
        for (int k = 0; k < 64; k++)
            acc += sf[n * 64 + k] * sw1[k * 128 + t];
        sz[n * 128 + t] = fmaxf(acc, 0.f);
    }
    __syncthreads();

    for (int oi = tid; oi < FCNPB * NCLS; oi += 256) {
        int n = oi / NCLS;
        int c = oi % NCLS;
        float acc = b2[c];
#pragma unroll
        for (int j = 0; j < 128; j++)
            acc += sz[n * 128 + j] * sw2[j * 12 + c];
        out[(size_t)(mi0 + n) * NCLS + c] = acc;
    }
}

// ---------------- launch -----------------------------------------------------
extern "C" void kernel_launch(void* const* d_in, const int* in_sizes, int n_in,
                              void* d_out, int out_size) {
    const float* x      = (const float*)d_in[0];
    const void*  edges  = d_in[1];
    const void*  mask   = d_in[2];
    const float* W1     = (const float*)d_in[3];
    const float* a_src1 = (const float*)d_in[4];
    const float* a_dst1 = (const float*)d_in[5];
    const float* b1     = (const float*)d_in[6];
    const float* W2     = (const float*)d_in[7];
    const float* a_src2 = (const float*)d_in[8];
    const float* a_dst2 = (const float*)d_in[9];
    const float* b2     = (const float*)d_in[10];
    const float* fc1_w  = (const float*)d_in[11];
    const float* fc1_b  = (const float*)d_in[12];
    const float* fc2_w  = (const float*)d_in[13];
    const float* fc2_b  = (const float*)d_in[14];
    float* out = (float*)d_out;

    __half* g_hh_p;   cudaGetSymbolAddress((void**)&g_hh_p, g_hh);
    __half* g_w1h_p;  cudaGetSymbolAddress((void**)&g_w1h_p, g_w1h);
    __half* g_w2h_p;  cudaGetSymbolAddress((void**)&g_w2h_p, g_w2h);
    float* g_out1_p;  cudaGetSymbolAddress((void**)&g_out1_p, g_out1);
    float* g_out2_p;  cudaGetSymbolAddress((void**)&g_out2_p, g_out2);

    // smem: A 128*256 + B 128*ROWB + sa/sd + sal(256 floats)
    const int smem128 = 128 * 256 + 128 * 256 + 2 * 128 * 4 + 256 * 4;         // 67584
    const int smem64  = 128 * 256 + 128 * 128 + 2 * 64 * 4 + 256 * 4;          // 50688
    const int smemFc  = (64 * 128 + 128 * 12 + FCNPB * 64 + FCNPB * 128) * 4;  // 63488
    cudaFuncSetAttribute(mma_gemm_kernel<128>, cudaFuncAttributeMaxDynamicSharedMemorySize, smem128);
    cudaFuncSetAttribute(mma_gemm_kernel<64>,  cudaFuncAttributeMaxDynamicSharedMemorySize, smem64);
    cudaFuncSetAttribute(fc_kernel, cudaFuncAttributeMaxDynamicSharedMemorySize, smemFc);

    const int warpBlocks = (NN * 32 + 255) / 256;
    const int gemmBlocks = (NN + 127) / 128;

    convert_hist_kernel<<<(EE + MM + WCONV4 + 255) / 256, 256>>>(edges, mask, W1, W2);
    scan1_kernel<<<NB1, 1024>>>();
    scan3_kernel<<<(NN + 255) / 256, 256>>>();
    mma_gemm_kernel<128><<<gemmBlocks, 256, smem128>>>(x, g_w1h_p, a_src1, a_dst1, g_hh_p, NN);
    scatter_kernel<<<(ETOT + 255) / 256, 256>>>(edges);
    agg_kernel<H1D><<<warpBlocks, 256>>>(g_hh_p, b1, g_out1_p);

    mma_gemm_kernel<64><<<gemmBlocks, 256, smem64>>>(g_out1_p, g_w2h_p, a_src2, a_dst2, g_hh_p, NN);
    agg_kernel<H2D><<<warpBlocks, 256>>>(g_hh_p, b2, g_out2_p);

    fc_kernel<<<MM / FCNPB, 256, smemFc>>>(g_out2_p, fc1_w, fc1_b, fc2_w, fc2_b, out);
}